// round 4
// baseline (speedup 1.0000x reference)
#include <cuda_runtime.h>
#include <cuda_bf16.h>
#include <mma.h>

using namespace nvcuda;

// Problem constants (shapes are fixed by the reference)
#define BATCH 4
#define LQ    4096
#define CDIM  384
#define NH    6
#define NP    4
#define DH    64
#define HL    64
#define WL    64
#define LV    (HL*WL)          // 4096
#define MROW  (BATCH*LQ)       // 16384  (== BATCH*LV)

// ---------------- scratch (static device globals; no runtime allocation) ----
__device__ __nv_bfloat16 g_fnorm[MROW * CDIM];     // LN(feat) in bf16 (GEMM A)
__device__ float         g_qnorm[MROW * CDIM];     // LN(query) fp32 (proj input)
__device__ float         g_value[MROW * CDIM];     // value = fnorm@Wv+bv
__device__ __nv_bfloat16 g_samp [MROW * CDIM];     // sampled attn (GEMM A)
__device__ float         g_loc  [MROW * NH * NP * 2];
__device__ float         g_attw [MROW * NH * NP];
__device__ __nv_bfloat16 g_WvB  [CDIM * CDIM];
__device__ __nv_bfloat16 g_WoutB[CDIM * CDIM];

// ---------------------------------------------------------------- utilities
__device__ __forceinline__ float warpReduceSum(float v) {
    #pragma unroll
    for (int o = 16; o > 0; o >>= 1) v += __shfl_xor_sync(0xffffffffu, v, o);
    return v;
}

// ------------------------------------------------------------- layernorm
// one block per row, 128 threads, 3 elements per thread
template<bool TO_BF16>
__global__ void ln_kernel(const float* __restrict__ x,
                          const float* __restrict__ g,
                          const float* __restrict__ b)
{
    const int row = blockIdx.x;
    const float* xr = x + (size_t)row * CDIM;
    const int t = threadIdx.x;

    float v0 = xr[t], v1 = xr[t + 128], v2 = xr[t + 256];
    float s  = v0 + v1 + v2;
    float sq = v0*v0 + v1*v1 + v2*v2;

    __shared__ float sh[8];
    s  = warpReduceSum(s);
    sq = warpReduceSum(sq);
    const int w = t >> 5;
    if ((t & 31) == 0) { sh[w] = s; sh[w + 4] = sq; }
    __syncthreads();
    if (t < 32) {
        float a = (t < 4) ? sh[t]     : 0.f;
        float c = (t < 4) ? sh[t + 4] : 0.f;
        a = warpReduceSum(a);
        c = warpReduceSum(c);
        if (t == 0) { sh[0] = a; sh[1] = c; }
    }
    __syncthreads();

    const float mu   = sh[0] * (1.f / CDIM);
    const float var  = sh[1] * (1.f / CDIM) - mu * mu;
    const float rstd = rsqrtf(var + 1e-6f);

    #pragma unroll
    for (int e = 0; e < 3; e++) {
        const int i = t + e * 128;
        const float v = (e == 0) ? v0 : (e == 1) ? v1 : v2;
        const float o = (v - mu) * rstd * g[i] + b[i];
        if (TO_BF16) g_fnorm[(size_t)row * CDIM + i] = __float2bfloat16(o);
        else         g_qnorm[(size_t)row * CDIM + i] = o;
    }
}

// ------------------------------------------------------- weight conversion
__global__ void cvt_kernel(const float* __restrict__ Wv,
                           const float* __restrict__ Wout)
{
    const int i = blockIdx.x * blockDim.x + threadIdx.x;
    if (i < CDIM * CDIM) {
        g_WvB[i]   = __float2bfloat16(Wv[i]);
        g_WoutB[i] = __float2bfloat16(Wout[i]);
    }
}

// ---------------------------------------------- bf16 WMMA GEMM  (M x 384 x 384)
// BM=128, BN=128, BK=16; 8 warps: 4 (M) x 2 (N); each warp 32x64 = 2x4 frags
// EPI==0 : g_value = g_fnorm @ g_WvB + bias
// EPI==1 : out     = query + gamma * (g_samp @ g_WoutB + bias)
template<int EPI>
__global__ __launch_bounds__(256)
void gemm_kernel(const float* __restrict__ bias,
                 const float* __restrict__ query,
                 const float* __restrict__ gamma,
                 float* __restrict__ out)
{
    const __nv_bfloat16* __restrict__ A  = (EPI == 0) ? g_fnorm : g_samp;
    const __nv_bfloat16* __restrict__ Bm = (EPI == 0) ? g_WvB   : g_WoutB;
    float* __restrict__ dst              = (EPI == 0) ? g_value : out;

    __shared__ __nv_bfloat16 As[128][16];
    __shared__ __nv_bfloat16 Bs[16][128];
    __shared__ float         Cs[8][256];

    const int bm   = blockIdx.x * 128;
    const int bn   = blockIdx.y * 128;
    const int tid  = threadIdx.x;
    const int wid  = tid >> 5;
    const int lane = tid & 31;
    const int wm   = wid & 3;   // 0..3 -> 32 rows each
    const int wn   = wid >> 2;  // 0..1 -> 64 cols each

    wmma::fragment<wmma::accumulator, 16, 16, 16, float> acc[2][4];
    #pragma unroll
    for (int i = 0; i < 2; i++)
        #pragma unroll
        for (int j = 0; j < 4; j++)
            wmma::fill_fragment(acc[i][j], 0.0f);

    const int am  = tid >> 1;           // 0..127
    const int ak  = (tid & 1) << 3;     // 0 or 8
    const int bk  = tid >> 4;           // 0..15
    const int bn8 = (tid & 15) << 3;    // 0..120

    for (int k0 = 0; k0 < CDIM; k0 += 16) {
        *(float4*)&As[am][ak]  = *(const float4*)(A  + (size_t)(bm + am) * CDIM + k0 + ak);
        *(float4*)&Bs[bk][bn8] = *(const float4*)(Bm + (size_t)(k0 + bk) * CDIM + bn + bn8);
        __syncthreads();

        wmma::fragment<wmma::matrix_a, 16, 16, 16, __nv_bfloat16, wmma::row_major> af[2];
        wmma::fragment<wmma::matrix_b, 16, 16, 16, __nv_bfloat16, wmma::row_major> bf;
        wmma::load_matrix_sync(af[0], &As[wm * 32][0],      16);
        wmma::load_matrix_sync(af[1], &As[wm * 32 + 16][0], 16);
        #pragma unroll
        for (int j = 0; j < 4; j++) {
            wmma::load_matrix_sync(bf, &Bs[0][wn * 64 + j * 16], 128);
            wmma::mma_sync(acc[0][j], af[0], bf, acc[0][j]);
            wmma::mma_sync(acc[1][j], af[1], bf, acc[1][j]);
        }
        __syncthreads();
    }

    // epilogue: stage each 16x16 fragment through smem, apply bias / residual
    #pragma unroll
    for (int im = 0; im < 2; im++) {
        #pragma unroll
        for (int j = 0; j < 4; j++) {
            wmma::store_matrix_sync(Cs[wid], acc[im][j], 16, wmma::mem_row_major);
            __syncwarp();
            const int r  = lane >> 1;
            const int c0 = (lane & 1) << 3;
            const int gm = bm + wm * 32 + im * 16 + r;
            const int gn = bn + wn * 64 + j * 16 + c0;
            #pragma unroll
            for (int cc = 0; cc < 8; cc++) {
                const float v = Cs[wid][r * 16 + c0 + cc];
                const int   n = gn + cc;
                const size_t idx = (size_t)gm * CDIM + n;
                if (EPI == 0) dst[idx] = v + bias[n];
                else          dst[idx] = query[idx] + gamma[n] * (v + bias[n]);
            }
            __syncwarp();
        }
    }
}

// ------------------------------------------- projection + softmax + locations
// one block per query row; 128 threads (72 compute lanes)
__global__ __launch_bounds__(128)
void proj_kernel(const float* __restrict__ Wo, const float* __restrict__ bo,
                 const float* __restrict__ Wa, const float* __restrict__ ba,
                 const float* __restrict__ refp)
{
    const int row = blockIdx.x;
    __shared__ float qs[CDIM];
    __shared__ float s[72];

    for (int i = threadIdx.x; i < CDIM; i += 128)
        qs[i] = g_qnorm[(size_t)row * CDIM + i];
    __syncthreads();

    const int j = threadIdx.x;
    if (j < 48) {
        float acc = bo[j];
        const float* w = Wo + j;
        #pragma unroll 4
        for (int k = 0; k < CDIM; k++) acc += qs[k] * __ldg(w + k * 48);
        s[j] = acc;
    } else if (j < 72) {
        const int ja = j - 48;
        float acc = ba[ja];
        const float* w = Wa + ja;
        #pragma unroll 4
        for (int k = 0; k < CDIM; k++) acc += qs[k] * __ldg(w + k * 24);
        s[j] = acc;
    }
    __syncthreads();

    if (j < NH) {  // softmax over the 4 points of head j
        float m = -1e30f;
        #pragma unroll
        for (int p = 0; p < NP; p++) m = fmaxf(m, s[48 + j * NP + p]);
        float e[NP], sum = 0.f;
        #pragma unroll
        for (int p = 0; p < NP; p++) { e[p] = __expf(s[48 + j * NP + p] - m); sum += e[p]; }
        const float inv = 1.f / sum;
        #pragma unroll
        for (int p = 0; p < NP; p++)
            g_attw[(size_t)row * (NH * NP) + j * NP + p] = e[p] * inv;
    }
    if (j < 48) {  // loc = ref + offset / [W, H]   (W == H == 64)
        const int comp = j & 1;
        const float ref = refp[(size_t)row * 2 + comp];
        g_loc[(size_t)row * 48 + j] = ref + s[j] * (1.f / 64.f);
    }
}

// --------------------------------------------------------- bilinear sampling
__device__ __forceinline__ float corner_val(const float* vbase, int xi, int yi, float w)
{
    if (xi < 0 || xi >= WL || yi < 0 || yi >= HL) return 0.f;
    return w * vbase[(size_t)(yi * WL + xi) * CDIM];
}

// blockDim (64, 4): lane = channel d, y = (row,head) unit
__global__ __launch_bounds__(256)
void sample_kernel()
{
    const int d = threadIdx.x;                       // 0..63
    const int u = blockIdx.x * 4 + threadIdx.y;      // 0 .. MROW*NH-1
    const int h   = u % NH;
    const int row = u / NH;                          // b*LQ + lq
    const int b   = row >> 12;                       // / 4096

    const float* vbase = g_value + (size_t)b * LV * CDIM + h * DH + d;
    float acc = 0.f;

    #pragma unroll
    for (int p = 0; p < NP; p++) {
        const float lx = g_loc[(size_t)row * 48 + h * 8 + p * 2 + 0];
        const float ly = g_loc[(size_t)row * 48 + h * 8 + p * 2 + 1];
        const float w  = g_attw[(size_t)row * 24 + h * 4 + p];
        const float x = lx * (float)WL - 0.5f;
        const float y = ly * (float)HL - 0.5f;
        const float x0f = floorf(x), y0f = floorf(y);
        const int   x0 = (int)x0f, y0 = (int)y0f;
        const float wx = x - x0f, wy = y - y0f;
        acc += corner_val(vbase, x0,     y0,     (1.f - wx) * (1.f - wy) * w);
        acc += corner_val(vbase, x0 + 1, y0,     wx         * (1.f - wy) * w);
        acc += corner_val(vbase, x0,     y0 + 1, (1.f - wx) * wy         * w);
        acc += corner_val(vbase, x0 + 1, y0 + 1, wx         * wy         * w);
    }
    g_samp[(size_t)row * CDIM + h * DH + d] = __float2bfloat16(acc);
}

// ------------------------------------------------------------------- launch
// (resubmission of R2 kernel: R2 bench was an infra failure, no kernel signal)
extern "C" void kernel_launch(void* const* d_in, const int* in_sizes, int n_in,
                              void* d_out, int out_size)
{
    const float* query  = (const float*)d_in[0];
    const float* refp   = (const float*)d_in[1];
    const float* feat   = (const float*)d_in[2];
    // d_in[3] spatial_shapes, d_in[4] level_start_index: constants, unused
    const float* ln_q_g = (const float*)d_in[5];
    const float* ln_q_b = (const float*)d_in[6];
    const float* ln_f_g = (const float*)d_in[7];
    const float* ln_f_b = (const float*)d_in[8];
    const float* gamma  = (const float*)d_in[9];
    const float* Wv     = (const float*)d_in[10];
    const float* bv     = (const float*)d_in[11];
    const float* Wo     = (const float*)d_in[12];
    const float* bo     = (const float*)d_in[13];
    const float* Wa     = (const float*)d_in[14];
    const float* ba     = (const float*)d_in[15];
    const float* Wout   = (const float*)d_in[16];
    const float* bout   = (const float*)d_in[17];
    float* out = (float*)d_out;

    // 1. layernorms
    ln_kernel<false><<<MROW, 128>>>(query, ln_q_g, ln_q_b);   // -> g_qnorm (fp32)
    ln_kernel<true ><<<MROW, 128>>>(feat,  ln_f_g, ln_f_b);   // -> g_fnorm (bf16)

    // 2. weights to bf16
    cvt_kernel<<<(CDIM * CDIM + 255) / 256, 256>>>(Wv, Wout);

    // 3. value = LN(feat) @ Wv + bv
    gemm_kernel<0><<<dim3(MROW / 128, CDIM / 128), 256>>>(bv, nullptr, nullptr, nullptr);

    // 4. offsets / attention weights / sampling locations
    proj_kernel<<<MROW, 128>>>(Wo, bo, Wa, ba, refp);

    // 5. deformable bilinear sampling
    sample_kernel<<<(MROW * NH) / 4, dim3(64, 4)>>>();

    // 6. out = query + gamma * (samp @ Wout + bout)
    gemm_kernel<1><<<dim3(MROW / 128, CDIM / 128), 256>>>(bout, query, gamma, out);
}

// round 11
// speedup vs baseline: 1.8886x; 1.8886x over previous
#include <cuda_runtime.h>
#include <cuda_bf16.h>
#include <mma.h>
#include <cstdint>

using namespace nvcuda;

#define BATCH 4
#define LQ    4096
#define CDIM  384
#define NH    6
#define NP    4
#define DH    64
#define HL    64
#define WL    64
#define LV    (HL*WL)          // 4096
#define MROW  (BATCH*LQ)       // 16384
#define NPROJ 80               // 48 offsets + 24 attn logits + 8 pad

// ---------------- scratch (static device globals) ---------------------------
__device__ __nv_bfloat16 g_fnorm[MROW * CDIM];     // LN(feat)  bf16
__device__ __nv_bfloat16 g_qnorm[MROW * CDIM];     // LN(query) bf16
__device__ __nv_bfloat16 g_value[MROW * CDIM];     // value = fnorm@Wv+bv (bf16)
__device__ __nv_bfloat16 g_samp [MROW * CDIM];     // sampled attention (bf16)
__device__ float         g_s    [MROW * NPROJ];    // raw proj logits (no bias)
__device__ __nv_bfloat16 g_WvB  [CDIM * CDIM];
__device__ __nv_bfloat16 g_WoutB[CDIM * CDIM];
__device__ __nv_bfloat16 g_Wproj[CDIM * NPROJ];    // [Wo | Wa | 0pad]

// ---------------------------------------------------------------- cp.async
__device__ __forceinline__ void cp_async16(void* smem, const void* gmem) {
    unsigned int s = (unsigned int)__cvta_generic_to_shared(smem);
    asm volatile("cp.async.cg.shared.global [%0], [%1], 16;\n" :: "r"(s), "l"(gmem));
}
__device__ __forceinline__ void cp_commit() {
    asm volatile("cp.async.commit_group;\n");
}
template<int N> __device__ __forceinline__ void cp_wait() {
    asm volatile("cp.async.wait_group %0;\n" :: "n"(N));
}

__device__ __forceinline__ float warpReduceSum(float v) {
    #pragma unroll
    for (int o = 16; o > 0; o >>= 1) v += __shfl_xor_sync(0xffffffffu, v, o);
    return v;
}

// ------------------------------------------------------------- layernorm
// one block per row, 128 threads, 3 elements/thread, bf16 out
template<int DST>   // 0 -> g_fnorm, 1 -> g_qnorm
__global__ void ln_kernel(const float* __restrict__ x,
                          const float* __restrict__ g,
                          const float* __restrict__ b)
{
    __nv_bfloat16* dst = (DST == 0) ? g_fnorm : g_qnorm;
    const int row = blockIdx.x;
    const float* xr = x + (size_t)row * CDIM;
    const int t = threadIdx.x;

    float v0 = xr[t], v1 = xr[t + 128], v2 = xr[t + 256];
    float s  = v0 + v1 + v2;
    float sq = v0*v0 + v1*v1 + v2*v2;

    __shared__ float sh[8];
    s  = warpReduceSum(s);
    sq = warpReduceSum(sq);
    const int w = t >> 5;
    if ((t & 31) == 0) { sh[w] = s; sh[w + 4] = sq; }
    __syncthreads();
    if (t < 32) {
        float a = (t < 4) ? sh[t]     : 0.f;
        float c = (t < 4) ? sh[t + 4] : 0.f;
        a = warpReduceSum(a);
        c = warpReduceSum(c);
        if (t == 0) { sh[0] = a; sh[1] = c; }
    }
    __syncthreads();

    const float mu   = sh[0] * (1.f / CDIM);
    const float var  = sh[1] * (1.f / CDIM) - mu * mu;
    const float rstd = rsqrtf(var + 1e-6f);

    #pragma unroll
    for (int e = 0; e < 3; e++) {
        const int i = t + e * 128;
        const float v = (e == 0) ? v0 : (e == 1) ? v1 : v2;
        dst[(size_t)row * CDIM + i] = __float2bfloat16((v - mu) * rstd * g[i] + b[i]);
    }
}

// ------------------------------------------------------- weight conversion
__global__ void cvt_kernel(const float* __restrict__ Wv,
                           const float* __restrict__ Wout,
                           const float* __restrict__ Wo,
                           const float* __restrict__ Wa)
{
    const int i = blockIdx.x * blockDim.x + threadIdx.x;
    if (i < CDIM * CDIM) {
        g_WvB[i]   = __float2bfloat16(Wv[i]);
        g_WoutB[i] = __float2bfloat16(Wout[i]);
    }
    if (i < CDIM * NPROJ) {
        const int k = i / NPROJ, c = i % NPROJ;
        float v = 0.f;
        if (c < 48)      v = Wo[k * 48 + c];
        else if (c < 72) v = Wa[k * 24 + (c - 48)];
        g_Wproj[i] = __float2bfloat16(v);
    }
}

// ---------------------------------------------- bf16 WMMA GEMM  (16384x384x384)
// BM=128 BN=128 BK=32, 3-stage cp.async pipeline. 8 warps = 4(M) x 2(N),
// each warp 32x64 = 2x4 fragments. No smem aliasing: separate epilogue buffer.
// EPI==0 : g_value(bf16) = g_fnorm @ g_WvB + bias
// EPI==1 : out(fp32)     = query + gamma * (g_samp @ g_WoutB + bias)
template<int EPI>
__global__ __launch_bounds__(256)
void gemm_kernel(const float* __restrict__ bias,
                 const float* __restrict__ query,
                 const float* __restrict__ gamma,
                 float* __restrict__ out)
{
    const __nv_bfloat16* __restrict__ A  = (EPI == 0) ? g_fnorm : g_samp;
    const __nv_bfloat16* __restrict__ Bm = (EPI == 0) ? g_WvB   : g_WoutB;

    __shared__ __nv_bfloat16 sA[3][128 * 32];
    __shared__ __nv_bfloat16 sB[3][32 * 128];
    __shared__ float         sC[8][256];

    const int bm   = blockIdx.x * 128;
    const int bn   = blockIdx.y * 128;
    const int tid  = threadIdx.x;
    const int wid  = tid >> 5;
    const int lane = tid & 31;
    const int wm   = wid & 3;
    const int wn   = wid >> 2;

    // chunk maps (16B = 8 bf16). A tile 128x32 = 512 chunks, B tile 32x128 = 512.
    const int a_r0 = tid >> 2,            a_o0 = (tid & 3) << 3;
    const int a_r1 = (tid + 256) >> 2;
    const int b_r0 = tid >> 4,            b_o0 = (tid & 15) << 3;
    const int b_r1 = (tid + 256) >> 4;

    auto load_stage = [&](int st, int k0) {
        cp_async16(&sA[st][a_r0 * 32 + a_o0], A  + (size_t)(bm + a_r0) * CDIM + k0 + a_o0);
        cp_async16(&sA[st][a_r1 * 32 + a_o0], A  + (size_t)(bm + a_r1) * CDIM + k0 + a_o0);
        cp_async16(&sB[st][b_r0 * 128 + b_o0], Bm + (size_t)(k0 + b_r0) * CDIM + bn + b_o0);
        cp_async16(&sB[st][b_r1 * 128 + b_o0], Bm + (size_t)(k0 + b_r1) * CDIM + bn + b_o0);
        cp_commit();
    };

    wmma::fragment<wmma::accumulator, 16, 16, 16, float> acc[2][4];
    #pragma unroll
    for (int i = 0; i < 2; i++)
        #pragma unroll
        for (int j = 0; j < 4; j++)
            wmma::fill_fragment(acc[i][j], 0.0f);

    load_stage(0, 0);
    load_stage(1, 32);

    const int KIT = CDIM / 32;   // 12
    for (int k = 0; k < KIT; k++) {
        cp_wait<1>();
        __syncthreads();
        const int st = k % 3;

        if (k + 2 < KIT) load_stage((k + 2) % 3, (k + 2) * 32);
        else             cp_commit();   // keep pending-group count uniform

        #pragma unroll
        for (int kk = 0; kk < 2; kk++) {
            wmma::fragment<wmma::matrix_a, 16, 16, 16, __nv_bfloat16, wmma::row_major> af[2];
            wmma::fragment<wmma::matrix_b, 16, 16, 16, __nv_bfloat16, wmma::row_major> bf;
            wmma::load_matrix_sync(af[0], &sA[st][(wm * 32     ) * 32 + kk * 16], 32);
            wmma::load_matrix_sync(af[1], &sA[st][(wm * 32 + 16) * 32 + kk * 16], 32);
            #pragma unroll
            for (int j = 0; j < 4; j++) {
                wmma::load_matrix_sync(bf, &sB[st][(kk * 16) * 128 + wn * 64 + j * 16], 128);
                wmma::mma_sync(acc[0][j], af[0], bf, acc[0][j]);
                wmma::mma_sync(acc[1][j], af[1], bf, acc[1][j]);
            }
        }
    }

    // fully drain the async pipeline before the epilogue (defensive; cheap)
    cp_wait<0>();
    __syncthreads();

    #pragma unroll
    for (int im = 0; im < 2; im++) {
        #pragma unroll
        for (int j = 0; j < 4; j++) {
            wmma::store_matrix_sync(sC[wid], acc[im][j], 16, wmma::mem_row_major);
            __syncwarp();
            const int r  = lane >> 1;
            const int c0 = (lane & 1) << 3;
            const int gm = bm + wm * 32 + im * 16 + r;
            const int gn = bn + wn * 64 + j * 16 + c0;
            if (EPI == 0) {
                union { __nv_bfloat16 h[8]; uint4 u; } t;
                #pragma unroll
                for (int cc = 0; cc < 8; cc++)
                    t.h[cc] = __float2bfloat16(sC[wid][r * 16 + c0 + cc] + bias[gn + cc]);
                *(uint4*)&g_value[(size_t)gm * CDIM + gn] = t.u;
            } else {
                const size_t base = (size_t)gm * CDIM + gn;
                float4 q0 = *(const float4*)&query[base];
                float4 q1 = *(const float4*)&query[base + 4];
                float4 o0, o1;
                o0.x = q0.x + gamma[gn+0] * (sC[wid][r*16+c0+0] + bias[gn+0]);
                o0.y = q0.y + gamma[gn+1] * (sC[wid][r*16+c0+1] + bias[gn+1]);
                o0.z = q0.z + gamma[gn+2] * (sC[wid][r*16+c0+2] + bias[gn+2]);
                o0.w = q0.w + gamma[gn+3] * (sC[wid][r*16+c0+3] + bias[gn+3]);
                o1.x = q1.x + gamma[gn+4] * (sC[wid][r*16+c0+4] + bias[gn+4]);
                o1.y = q1.y + gamma[gn+5] * (sC[wid][r*16+c0+5] + bias[gn+5]);
                o1.z = q1.z + gamma[gn+6] * (sC[wid][r*16+c0+6] + bias[gn+6]);
                o1.w = q1.w + gamma[gn+7] * (sC[wid][r*16+c0+7] + bias[gn+7]);
                *(float4*)&out[base]     = o0;
                *(float4*)&out[base + 4] = o1;
            }
            __syncwarp();
        }
    }
}

// ------------------------------- projection GEMM: s = qnorm @ Wproj (16384x80x384)
// BM=128 BN=80 BK=32, 2-stage cp.async. 8 warps, each 16 rows x 80 cols (5 frags).
__global__ __launch_bounds__(256)
void projgemm_kernel()
{
    __shared__ __nv_bfloat16 As[2][128 * 32];
    __shared__ __nv_bfloat16 Bs[2][32 * NPROJ];
    __shared__ float         Cs[8][256];

    const int bm   = blockIdx.x * 128;
    const int tid  = threadIdx.x;
    const int wid  = tid >> 5;
    const int lane = tid & 31;

    const int a_r0 = tid >> 2,         a_o = (tid & 3) << 3;
    const int a_r1 = (tid + 256) >> 2;

    auto load_stage = [&](int st, int k0) {
        cp_async16(&As[st][a_r0 * 32 + a_o], g_qnorm + (size_t)(bm + a_r0) * CDIM + k0 + a_o);
        cp_async16(&As[st][a_r1 * 32 + a_o], g_qnorm + (size_t)(bm + a_r1) * CDIM + k0 + a_o);
        // B tile 32x80 bf16 = 320 chunks of 16B
        {
            const int c = tid;              // 0..255
            if (c < 320) {
                const int r = c / 10, o = (c % 10) << 3;
                cp_async16(&Bs[st][r * NPROJ + o], g_Wproj + (size_t)(k0 + r) * NPROJ + o);
            }
            const int c2 = tid + 256;       // 256..511 -> only 256..319 valid
            if (c2 < 320) {
                const int r = c2 / 10, o = (c2 % 10) << 3;
                cp_async16(&Bs[st][r * NPROJ + o], g_Wproj + (size_t)(k0 + r) * NPROJ + o);
            }
        }
        cp_commit();
    };

    wmma::fragment<wmma::accumulator, 16, 16, 16, float> acc[5];
    #pragma unroll
    for (int j = 0; j < 5; j++) wmma::fill_fragment(acc[j], 0.0f);

    load_stage(0, 0);
    const int KIT = CDIM / 32;   // 12
    for (int k = 0; k < KIT; k++) {
        cp_wait<0>();
        __syncthreads();
        const int st = k & 1;
        if (k + 1 < KIT) load_stage((k + 1) & 1, (k + 1) * 32);

        #pragma unroll
        for (int kk = 0; kk < 2; kk++) {
            wmma::fragment<wmma::matrix_a, 16, 16, 16, __nv_bfloat16, wmma::row_major> af;
            wmma::fragment<wmma::matrix_b, 16, 16, 16, __nv_bfloat16, wmma::row_major> bf;
            wmma::load_matrix_sync(af, &As[st][(wid * 16) * 32 + kk * 16], 32);
            #pragma unroll
            for (int j = 0; j < 5; j++) {
                wmma::load_matrix_sync(bf, &Bs[st][(kk * 16) * NPROJ + j * 16], NPROJ);
                wmma::mma_sync(acc[j], af, bf, acc[j]);
            }
        }
    }

    cp_wait<0>();
    __syncthreads();

    #pragma unroll
    for (int j = 0; j < 5; j++) {
        wmma::store_matrix_sync(Cs[wid], acc[j], 16, wmma::mem_row_major);
        __syncwarp();
        const int r  = lane >> 1;
        const int c0 = (lane & 1) << 3;
        const int gm = bm + wid * 16 + r;
        const int gn = j * 16 + c0;
        #pragma unroll
        for (int cc = 0; cc < 8; cc++)
            g_s[(size_t)gm * NPROJ + gn + cc] = Cs[wid][r * 16 + c0 + cc];
        __syncwarp();
    }
}

// ------------------------------ sampling (softmax + locations fused) --------
// blockDim (64,4): lane = channel d, y-slot = (row,head) unit
__global__ __launch_bounds__(256)
void sample_kernel(const float* __restrict__ bo,
                   const float* __restrict__ ba,
                   const float* __restrict__ refp)
{
    const int d = threadIdx.x;                       // 0..63
    const int u = blockIdx.x * 4 + threadIdx.y;      // 0 .. MROW*NH-1
    const int h   = u % NH;
    const int row = u / NH;
    const int b   = row >> 12;

    const float rx = refp[(size_t)row * 2 + 0] * 64.f - 0.5f;
    const float ry = refp[(size_t)row * 2 + 1] * 64.f - 0.5f;
    const float* srow = g_s + (size_t)row * NPROJ;

    // softmax over the head's 4 attention logits (redundant per lane; L1 broadcast)
    float aw[NP]; float m = -1e30f;
    #pragma unroll
    for (int p = 0; p < NP; p++) {
        aw[p] = srow[48 + h * NP + p] + ba[h * NP + p];
        m = fmaxf(m, aw[p]);
    }
    float ssum = 0.f;
    #pragma unroll
    for (int p = 0; p < NP; p++) { aw[p] = __expf(aw[p] - m); ssum += aw[p]; }
    const float inv = 1.f / ssum;

    const __nv_bfloat16* vb = g_value + (size_t)b * LV * CDIM + h * DH + d;
    float acc = 0.f;

    #pragma unroll
    for (int p = 0; p < NP; p++) {
        // loc*64 - 0.5 == ref*64 + offset - 0.5 (W == H == 64 cancels the /64)
        const float x = rx + srow[h * 8 + p * 2 + 0] + bo[h * 8 + p * 2 + 0];
        const float y = ry + srow[h * 8 + p * 2 + 1] + bo[h * 8 + p * 2 + 1];
        const float w = aw[p] * inv;
        const float x0f = floorf(x), y0f = floorf(y);
        const int   x0 = (int)x0f,  y0 = (int)y0f;
        const float wx = x - x0f,   wy = y - y0f;

        const bool xin0 = (x0 >= 0) & (x0 < WL), xin1 = (x0+1 >= 0) & (x0+1 < WL);
        const bool yin0 = (y0 >= 0) & (y0 < HL), yin1 = (y0+1 >= 0) & (y0+1 < HL);
        if (xin0 & yin0) acc += (1.f-wx)*(1.f-wy)*w * __bfloat162float(vb[(size_t)(y0    *WL + x0  ) * CDIM]);
        if (xin1 & yin0) acc += (wx    )*(1.f-wy)*w * __bfloat162float(vb[(size_t)(y0    *WL + x0+1) * CDIM]);
        if (xin0 & yin1) acc += (1.f-wx)*(wy    )*w * __bfloat162float(vb[(size_t)((y0+1)*WL + x0  ) * CDIM]);
        if (xin1 & yin1) acc += (wx    )*(wy    )*w * __bfloat162float(vb[(size_t)((y0+1)*WL + x0+1) * CDIM]);
    }
    g_samp[(size_t)row * CDIM + h * DH + d] = __float2bfloat16(acc);
}

// ------------------------------------------------------------------- launch
extern "C" void kernel_launch(void* const* d_in, const int* in_sizes, int n_in,
                              void* d_out, int out_size)
{
    const float* query  = (const float*)d_in[0];
    const float* refp   = (const float*)d_in[1];
    const float* feat   = (const float*)d_in[2];
    const float* ln_q_g = (const float*)d_in[5];
    const float* ln_q_b = (const float*)d_in[6];
    const float* ln_f_g = (const float*)d_in[7];
    const float* ln_f_b = (const float*)d_in[8];
    const float* gamma  = (const float*)d_in[9];
    const float* Wv     = (const float*)d_in[10];
    const float* bv     = (const float*)d_in[11];
    const float* Wo     = (const float*)d_in[12];
    const float* bo     = (const float*)d_in[13];
    const float* Wa     = (const float*)d_in[14];
    const float* ba     = (const float*)d_in[15];
    const float* Wout   = (const float*)d_in[16];
    const float* bout   = (const float*)d_in[17];
    float* out = (float*)d_out;

    ln_kernel<0><<<MROW, 128>>>(feat,  ln_f_g, ln_f_b);          // -> g_fnorm
    ln_kernel<1><<<MROW, 128>>>(query, ln_q_g, ln_q_b);          // -> g_qnorm
    cvt_kernel<<<(CDIM * CDIM + 255) / 256, 256>>>(Wv, Wout, Wo, Wa);

    gemm_kernel<0><<<dim3(MROW / 128, CDIM / 128), 256>>>(bv, nullptr, nullptr, nullptr);
    projgemm_kernel<<<MROW / 128, 256>>>();
    sample_kernel<<<(MROW * NH) / 4, dim3(64, 4)>>>(bo, ba, refp);
    gemm_kernel<1><<<dim3(MROW / 128, CDIM / 128), 256>>>(bout, query, gamma, out);
}

// round 12
// speedup vs baseline: 2.5733x; 1.3625x over previous
#include <cuda_runtime.h>
#include <cuda_bf16.h>
#include <mma.h>
#include <cstdint>

using namespace nvcuda;

#define BATCH 4
#define LQ    4096
#define CDIM  384
#define NH    6
#define NP    4
#define DH    64
#define HL    64
#define WL    64
#define LV    (HL*WL)          // 4096
#define MROW  (BATCH*LQ)       // 16384
#define NPROJ 80               // 48 offsets + 24 attn logits + 8 pad

// padded shared strides (conflict-free LDSM phases; all multiples of 16B)
#define SAP   40               // A tile ldm (elems): 80B row stride
#define SBP   136              // B tile ldm (elems): 272B row stride
#define SPP   88               // proj B tile ldm (elems): 176B row stride

// ---------------- scratch (static device globals) ---------------------------
__device__ __nv_bfloat16 g_fnorm[MROW * CDIM];     // LN(feat)  bf16
__device__ __nv_bfloat16 g_qnorm[MROW * CDIM];     // LN(query) bf16
__device__ __nv_bfloat16 g_value[MROW * CDIM];     // value = fnorm@Wv+bv (bf16)
__device__ __nv_bfloat16 g_samp [MROW * CDIM];     // sampled attention (bf16)
__device__ float         g_s    [MROW * NPROJ];    // raw proj logits (no bias)
__device__ __nv_bfloat16 g_WvB  [CDIM * CDIM];
__device__ __nv_bfloat16 g_WoutB[CDIM * CDIM];
__device__ __nv_bfloat16 g_Wproj[CDIM * NPROJ];    // [Wo | Wa | 0pad]

// ---------------------------------------------------------------- cp.async
__device__ __forceinline__ void cp_async16(void* smem, const void* gmem) {
    unsigned int s = (unsigned int)__cvta_generic_to_shared(smem);
    asm volatile("cp.async.cg.shared.global [%0], [%1], 16;\n" :: "r"(s), "l"(gmem));
}
__device__ __forceinline__ void cp_commit() {
    asm volatile("cp.async.commit_group;\n");
}
template<int N> __device__ __forceinline__ void cp_wait() {
    asm volatile("cp.async.wait_group %0;\n" :: "n"(N));
}

__device__ __forceinline__ float warpReduceSum(float v) {
    #pragma unroll
    for (int o = 16; o > 0; o >>= 1) v += __shfl_xor_sync(0xffffffffu, v, o);
    return v;
}

// ------------------------------------------------------------- layernorm
// one merged launch: blocks [0, MROW) -> feat, [MROW, 2*MROW) -> query
__global__ void ln_kernel(const float* __restrict__ feat,
                          const float* __restrict__ query,
                          const float* __restrict__ gf, const float* __restrict__ bf_,
                          const float* __restrict__ gq, const float* __restrict__ bq)
{
    const bool isq = blockIdx.x >= MROW;
    const int row  = isq ? (blockIdx.x - MROW) : blockIdx.x;
    const float* __restrict__ x = isq ? query : feat;
    const float* __restrict__ g = isq ? gq : gf;
    const float* __restrict__ b = isq ? bq : bf_;
    __nv_bfloat16* dst = isq ? g_qnorm : g_fnorm;

    const float* xr = x + (size_t)row * CDIM;
    const int t = threadIdx.x;

    float v0 = xr[t], v1 = xr[t + 128], v2 = xr[t + 256];
    float s  = v0 + v1 + v2;
    float sq = v0*v0 + v1*v1 + v2*v2;

    __shared__ float sh[8];
    s  = warpReduceSum(s);
    sq = warpReduceSum(sq);
    const int w = t >> 5;
    if ((t & 31) == 0) { sh[w] = s; sh[w + 4] = sq; }
    __syncthreads();
    if (t < 32) {
        float a = (t < 4) ? sh[t]     : 0.f;
        float c = (t < 4) ? sh[t + 4] : 0.f;
        a = warpReduceSum(a);
        c = warpReduceSum(c);
        if (t == 0) { sh[0] = a; sh[1] = c; }
    }
    __syncthreads();

    const float mu   = sh[0] * (1.f / CDIM);
    const float var  = sh[1] * (1.f / CDIM) - mu * mu;
    const float rstd = rsqrtf(var + 1e-6f);

    #pragma unroll
    for (int e = 0; e < 3; e++) {
        const int i = t + e * 128;
        const float v = (e == 0) ? v0 : (e == 1) ? v1 : v2;
        dst[(size_t)row * CDIM + i] = __float2bfloat16((v - mu) * rstd * g[i] + b[i]);
    }
}

// ------------------------------------------------------- weight conversion
__global__ void cvt_kernel(const float* __restrict__ Wv,
                           const float* __restrict__ Wout,
                           const float* __restrict__ Wo,
                           const float* __restrict__ Wa)
{
    const int i = blockIdx.x * blockDim.x + threadIdx.x;
    if (i < CDIM * CDIM) {
        g_WvB[i]   = __float2bfloat16(Wv[i]);
        g_WoutB[i] = __float2bfloat16(Wout[i]);
    }
    if (i < CDIM * NPROJ) {
        const int k = i / NPROJ, c = i % NPROJ;
        float v = 0.f;
        if (c < 48)      v = Wo[k * 48 + c];
        else if (c < 72) v = Wa[k * 24 + (c - 48)];
        g_Wproj[i] = __float2bfloat16(v);
    }
}

// ---------------------------------------------- bf16 WMMA GEMM  (16384x384x384)
// BM=128 BN=128 BK=32, 3-stage cp.async pipeline, padded (conflict-free) smem.
// 8 warps = 4(M) x 2(N), each warp 32x64 = 2x4 fragments.
// EPI==0 : g_value(bf16) = g_fnorm @ g_WvB + bias
// EPI==1 : out(fp32)     = query + gamma * (g_samp @ g_WoutB + bias)
template<int EPI>
__global__ __launch_bounds__(256)
void gemm_kernel(const float* __restrict__ bias,
                 const float* __restrict__ query,
                 const float* __restrict__ gamma,
                 float* __restrict__ out)
{
    const __nv_bfloat16* __restrict__ A  = (EPI == 0) ? g_fnorm : g_samp;
    const __nv_bfloat16* __restrict__ Bm = (EPI == 0) ? g_WvB   : g_WoutB;

    __shared__ __nv_bfloat16 sA[3][128 * SAP];
    __shared__ __nv_bfloat16 sB[3][32 * SBP];
    __shared__ float         sC[8][256];

    const int bm   = blockIdx.x * 128;
    const int bn   = blockIdx.y * 128;
    const int tid  = threadIdx.x;
    const int wid  = tid >> 5;
    const int lane = tid & 31;
    const int wm   = wid & 3;
    const int wn   = wid >> 2;

    // chunk maps (16B = 8 bf16). A tile 128x32 = 512 chunks, B tile 32x128 = 512.
    const int a_r0 = tid >> 2,            a_o0 = (tid & 3) << 3;
    const int a_r1 = (tid + 256) >> 2;
    const int b_r0 = tid >> 4,            b_o0 = (tid & 15) << 3;
    const int b_r1 = (tid + 256) >> 4;

    auto load_stage = [&](int st, int k0) {
        cp_async16(&sA[st][a_r0 * SAP + a_o0], A  + (size_t)(bm + a_r0) * CDIM + k0 + a_o0);
        cp_async16(&sA[st][a_r1 * SAP + a_o0], A  + (size_t)(bm + a_r1) * CDIM + k0 + a_o0);
        cp_async16(&sB[st][b_r0 * SBP + b_o0], Bm + (size_t)(k0 + b_r0) * CDIM + bn + b_o0);
        cp_async16(&sB[st][b_r1 * SBP + b_o0], Bm + (size_t)(k0 + b_r1) * CDIM + bn + b_o0);
        cp_commit();
    };

    wmma::fragment<wmma::accumulator, 16, 16, 16, float> acc[2][4];
    #pragma unroll
    for (int i = 0; i < 2; i++)
        #pragma unroll
        for (int j = 0; j < 4; j++)
            wmma::fill_fragment(acc[i][j], 0.0f);

    load_stage(0, 0);
    load_stage(1, 32);

    const int KIT = CDIM / 32;   // 12
    for (int k = 0; k < KIT; k++) {
        cp_wait<1>();
        __syncthreads();
        const int st = k % 3;

        if (k + 2 < KIT) load_stage((k + 2) % 3, (k + 2) * 32);
        else             cp_commit();   // keep pending-group count uniform

        #pragma unroll
        for (int kk = 0; kk < 2; kk++) {
            wmma::fragment<wmma::matrix_a, 16, 16, 16, __nv_bfloat16, wmma::row_major> af[2];
            wmma::fragment<wmma::matrix_b, 16, 16, 16, __nv_bfloat16, wmma::row_major> bf;
            wmma::load_matrix_sync(af[0], &sA[st][(wm * 32     ) * SAP + kk * 16], SAP);
            wmma::load_matrix_sync(af[1], &sA[st][(wm * 32 + 16) * SAP + kk * 16], SAP);
            #pragma unroll
            for (int j = 0; j < 4; j++) {
                wmma::load_matrix_sync(bf, &sB[st][(kk * 16) * SBP + wn * 64 + j * 16], SBP);
                wmma::mma_sync(acc[0][j], af[0], bf, acc[0][j]);
                wmma::mma_sync(acc[1][j], af[1], bf, acc[1][j]);
            }
        }
    }

    // fully drain the async pipeline before the epilogue
    cp_wait<0>();
    __syncthreads();

    #pragma unroll
    for (int im = 0; im < 2; im++) {
        #pragma unroll
        for (int j = 0; j < 4; j++) {
            wmma::store_matrix_sync(sC[wid], acc[im][j], 16, wmma::mem_row_major);
            __syncwarp();
            const int r  = lane >> 1;
            const int c0 = (lane & 1) << 3;
            const int gm = bm + wm * 32 + im * 16 + r;
            const int gn = bn + wn * 64 + j * 16 + c0;
            if (EPI == 0) {
                union { __nv_bfloat16 h[8]; uint4 u; } t;
                #pragma unroll
                for (int cc = 0; cc < 8; cc++)
                    t.h[cc] = __float2bfloat16(sC[wid][r * 16 + c0 + cc] + bias[gn + cc]);
                *(uint4*)&g_value[(size_t)gm * CDIM + gn] = t.u;
            } else {
                const size_t base = (size_t)gm * CDIM + gn;
                float4 q0 = *(const float4*)&query[base];
                float4 q1 = *(const float4*)&query[base + 4];
                float4 o0, o1;
                o0.x = q0.x + gamma[gn+0] * (sC[wid][r*16+c0+0] + bias[gn+0]);
                o0.y = q0.y + gamma[gn+1] * (sC[wid][r*16+c0+1] + bias[gn+1]);
                o0.z = q0.z + gamma[gn+2] * (sC[wid][r*16+c0+2] + bias[gn+2]);
                o0.w = q0.w + gamma[gn+3] * (sC[wid][r*16+c0+3] + bias[gn+3]);
                o1.x = q1.x + gamma[gn+4] * (sC[wid][r*16+c0+4] + bias[gn+4]);
                o1.y = q1.y + gamma[gn+5] * (sC[wid][r*16+c0+5] + bias[gn+5]);
                o1.z = q1.z + gamma[gn+6] * (sC[wid][r*16+c0+6] + bias[gn+6]);
                o1.w = q1.w + gamma[gn+7] * (sC[wid][r*16+c0+7] + bias[gn+7]);
                *(float4*)&out[base]     = o0;
                *(float4*)&out[base + 4] = o1;
            }
            __syncwarp();
        }
    }
}

// ------------------------------- projection GEMM: s = qnorm @ Wproj (16384x80x384)
// BM=128 BN=80 BK=32, 2-stage cp.async, padded smem. 8 warps, each 16x80 (5 frags).
__global__ __launch_bounds__(256)
void projgemm_kernel()
{
    __shared__ __nv_bfloat16 As[2][128 * SAP];
    __shared__ __nv_bfloat16 Bs[2][32 * SPP];
    __shared__ float         Cs[8][256];

    const int bm   = blockIdx.x * 128;
    const int tid  = threadIdx.x;
    const int wid  = tid >> 5;
    const int lane = tid & 31;

    const int a_r0 = tid >> 2,         a_o = (tid & 3) << 3;
    const int a_r1 = (tid + 256) >> 2;

    auto load_stage = [&](int st, int k0) {
        cp_async16(&As[st][a_r0 * SAP + a_o], g_qnorm + (size_t)(bm + a_r0) * CDIM + k0 + a_o);
        cp_async16(&As[st][a_r1 * SAP + a_o], g_qnorm + (size_t)(bm + a_r1) * CDIM + k0 + a_o);
        // B tile 32x80 bf16 = 320 chunks of 16B
        {
            const int c = tid;              // 0..255
            if (c < 320) {
                const int r = c / 10, o = (c % 10) << 3;
                cp_async16(&Bs[st][r * SPP + o], g_Wproj + (size_t)(k0 + r) * NPROJ + o);
            }
            const int c2 = tid + 256;       // 256..511 -> only 256..319 valid
            if (c2 < 320) {
                const int r = c2 / 10, o = (c2 % 10) << 3;
                cp_async16(&Bs[st][r * SPP + o], g_Wproj + (size_t)(k0 + r) * NPROJ + o);
            }
        }
        cp_commit();
    };

    wmma::fragment<wmma::accumulator, 16, 16, 16, float> acc[5];
    #pragma unroll
    for (int j = 0; j < 5; j++) wmma::fill_fragment(acc[j], 0.0f);

    load_stage(0, 0);
    const int KIT = CDIM / 32;   // 12
    for (int k = 0; k < KIT; k++) {
        cp_wait<0>();
        __syncthreads();
        const int st = k & 1;
        if (k + 1 < KIT) load_stage((k + 1) & 1, (k + 1) * 32);

        #pragma unroll
        for (int kk = 0; kk < 2; kk++) {
            wmma::fragment<wmma::matrix_a, 16, 16, 16, __nv_bfloat16, wmma::row_major> af;
            wmma::fragment<wmma::matrix_b, 16, 16, 16, __nv_bfloat16, wmma::row_major> bf;
            wmma::load_matrix_sync(af, &As[st][(wid * 16) * SAP + kk * 16], SAP);
            #pragma unroll
            for (int j = 0; j < 5; j++) {
                wmma::load_matrix_sync(bf, &Bs[st][(kk * 16) * SPP + j * 16], SPP);
                wmma::mma_sync(acc[j], af, bf, acc[j]);
            }
        }
    }

    cp_wait<0>();
    __syncthreads();

    #pragma unroll
    for (int j = 0; j < 5; j++) {
        wmma::store_matrix_sync(Cs[wid], acc[j], 16, wmma::mem_row_major);
        __syncwarp();
        const int r  = lane >> 1;
        const int c0 = (lane & 1) << 3;
        const int gm = bm + wid * 16 + r;
        const int gn = j * 16 + c0;
        #pragma unroll
        for (int cc = 0; cc < 8; cc++)
            g_s[(size_t)gm * NPROJ + gn + cc] = Cs[wid][r * 16 + c0 + cc];
        __syncwarp();
    }
}

// ------------------------------ sampling (softmax + locations fused) --------
// blockDim (64,4): lane = channel d, y-slot = (row,head) unit
__global__ __launch_bounds__(256)
void sample_kernel(const float* __restrict__ bo,
                   const float* __restrict__ ba,
                   const float* __restrict__ refp)
{
    const int d = threadIdx.x;                       // 0..63
    const int u = blockIdx.x * 4 + threadIdx.y;      // 0 .. MROW*NH-1
    const int h   = u % NH;
    const int row = u / NH;
    const int b   = row >> 12;

    const float rx = refp[(size_t)row * 2 + 0] * 64.f - 0.5f;
    const float ry = refp[(size_t)row * 2 + 1] * 64.f - 0.5f;
    const float* srow = g_s + (size_t)row * NPROJ;

    // softmax over the head's 4 attention logits (redundant per lane; L1 broadcast)
    float aw[NP]; float m = -1e30f;
    #pragma unroll
    for (int p = 0; p < NP; p++) {
        aw[p] = srow[48 + h * NP + p] + ba[h * NP + p];
        m = fmaxf(m, aw[p]);
    }
    float ssum = 0.f;
    #pragma unroll
    for (int p = 0; p < NP; p++) { aw[p] = __expf(aw[p] - m); ssum += aw[p]; }
    const float inv = 1.f / ssum;

    const __nv_bfloat16* vb = g_value + (size_t)b * LV * CDIM + h * DH + d;
    float acc = 0.f;

    #pragma unroll
    for (int p = 0; p < NP; p++) {
        // loc*64 - 0.5 == ref*64 + offset - 0.5 (W == H == 64 cancels the /64)
        const float x = rx + srow[h * 8 + p * 2 + 0] + bo[h * 8 + p * 2 + 0];
        const float y = ry + srow[h * 8 + p * 2 + 1] + bo[h * 8 + p * 2 + 1];
        const float w = aw[p] * inv;
        const float x0f = floorf(x), y0f = floorf(y);
        const int   x0 = (int)x0f,  y0 = (int)y0f;
        const float wx = x - x0f,   wy = y - y0f;

        const bool xin0 = (x0 >= 0) & (x0 < WL), xin1 = (x0+1 >= 0) & (x0+1 < WL);
        const bool yin0 = (y0 >= 0) & (y0 < HL), yin1 = (y0+1 >= 0) & (y0+1 < HL);
        if (xin0 & yin0) acc += (1.f-wx)*(1.f-wy)*w * __bfloat162float(vb[(size_t)(y0    *WL + x0  ) * CDIM]);
        if (xin1 & yin0) acc += (wx    )*(1.f-wy)*w * __bfloat162float(vb[(size_t)(y0    *WL + x0+1) * CDIM]);
        if (xin0 & yin1) acc += (1.f-wx)*(wy    )*w * __bfloat162float(vb[(size_t)((y0+1)*WL + x0  ) * CDIM]);
        if (xin1 & yin1) acc += (wx    )*(wy    )*w * __bfloat162float(vb[(size_t)((y0+1)*WL + x0+1) * CDIM]);
    }
    g_samp[(size_t)row * CDIM + h * DH + d] = __float2bfloat16(acc);
}

// ------------------------------------------------------------------- launch
extern "C" void kernel_launch(void* const* d_in, const int* in_sizes, int n_in,
                              void* d_out, int out_size)
{
    const float* query  = (const float*)d_in[0];
    const float* refp   = (const float*)d_in[1];
    const float* feat   = (const float*)d_in[2];
    const float* ln_q_g = (const float*)d_in[5];
    const float* ln_q_b = (const float*)d_in[6];
    const float* ln_f_g = (const float*)d_in[7];
    const float* ln_f_b = (const float*)d_in[8];
    const float* gamma  = (const float*)d_in[9];
    const float* Wv     = (const float*)d_in[10];
    const float* bv     = (const float*)d_in[11];
    const float* Wo     = (const float*)d_in[12];
    const float* bo     = (const float*)d_in[13];
    const float* Wa     = (const float*)d_in[14];
    const float* ba     = (const float*)d_in[15];
    const float* Wout   = (const float*)d_in[16];
    const float* bout   = (const float*)d_in[17];
    float* out = (float*)d_out;

    ln_kernel<<<2 * MROW, 128>>>(feat, query, ln_f_g, ln_f_b, ln_q_g, ln_q_b);
    cvt_kernel<<<(CDIM * CDIM + 255) / 256, 256>>>(Wv, Wout, Wo, Wa);

    gemm_kernel<0><<<dim3(MROW / 128, CDIM / 128), 256>>>(bv, nullptr, nullptr, nullptr);
    projgemm_kernel<<<MROW / 128, 256>>>();
    sample_kernel<<<(MROW * NH) / 4, dim3(64, 4)>>>(bo, ba, refp);
    gemm_kernel<1><<<dim3(MROW / 128, CDIM / 128), 256>>>(bout, query, gamma, out);
}

// round 13
// speedup vs baseline: 3.0098x; 1.1696x over previous
#include <cuda_runtime.h>
#include <cuda_bf16.h>
#include <mma.h>
#include <cstdint>

using namespace nvcuda;

#define BATCH 4
#define LQ    4096
#define CDIM  384
#define NH    6
#define NP    4
#define DH    64
#define HL    64
#define WL    64
#define LV    (HL*WL)          // 4096
#define MROW  (BATCH*LQ)       // 16384
#define NPROJ 80               // 48 offsets + 24 attn logits + 8 pad

// padded shared strides (conflict-free LDSM phases; all multiples of 16B)
#define SAP   40               // A tile ldm (elems): 80B row stride
#define SBP   136              // B tile ldm (elems): 272B row stride
#define SPP   88               // proj B tile ldm (elems): 176B row stride

// ---------------- scratch (static device globals) ---------------------------
__device__ __nv_bfloat16 g_fnorm[MROW * CDIM];     // LN(feat)  bf16
__device__ __nv_bfloat16 g_qnorm[MROW * CDIM];     // LN(query) bf16
__device__ __nv_bfloat16 g_value[MROW * CDIM];     // value = fnorm@Wv+bv (bf16)
__device__ __nv_bfloat16 g_samp [MROW * CDIM];     // sampled attention (bf16)
__device__ float         g_s    [MROW * NPROJ];    // raw proj logits (no bias)
__device__ __nv_bfloat16 g_WvB  [CDIM * CDIM];
__device__ __nv_bfloat16 g_WoutB[CDIM * CDIM];
__device__ __nv_bfloat16 g_Wproj[CDIM * NPROJ];    // [Wo | Wa | 0pad]

// ---------------------------------------------------------------- cp.async
__device__ __forceinline__ void cp_async16(void* smem, const void* gmem) {
    unsigned int s = (unsigned int)__cvta_generic_to_shared(smem);
    asm volatile("cp.async.cg.shared.global [%0], [%1], 16;\n" :: "r"(s), "l"(gmem));
}
__device__ __forceinline__ void cp_commit() {
    asm volatile("cp.async.commit_group;\n");
}
template<int N> __device__ __forceinline__ void cp_wait() {
    asm volatile("cp.async.wait_group %0;\n" :: "n"(N));
}

__device__ __forceinline__ float warpReduceSum(float v) {
    #pragma unroll
    for (int o = 16; o > 0; o >>= 1) v += __shfl_xor_sync(0xffffffffu, v, o);
    return v;
}

// ---------------------------------------------------------- shared layouts
struct GemmSmem {
    __nv_bfloat16 sA[3][128 * SAP];
    __nv_bfloat16 sB[3][32 * SBP];
    float         sC[8][256];
};
struct ProjSmem {
    __nv_bfloat16 As[2][128 * SAP];
    __nv_bfloat16 Bs[2][32 * SPP];
    float         Cs[8][256];
};
union MidSmem { GemmSmem g; ProjSmem p; };

// ------------------------------------------------------------- layernorm
// one merged launch: blocks [0, MROW) -> feat, [MROW, 2*MROW) -> query
__global__ void ln_kernel(const float* __restrict__ feat,
                          const float* __restrict__ query,
                          const float* __restrict__ gf, const float* __restrict__ bf_,
                          const float* __restrict__ gq, const float* __restrict__ bq)
{
    const bool isq = blockIdx.x >= MROW;
    const int row  = isq ? (blockIdx.x - MROW) : blockIdx.x;
    const float* __restrict__ x = isq ? query : feat;
    const float* __restrict__ g = isq ? gq : gf;
    const float* __restrict__ b = isq ? bq : bf_;
    __nv_bfloat16* dst = isq ? g_qnorm : g_fnorm;

    const float* xr = x + (size_t)row * CDIM;
    const int t = threadIdx.x;

    float v0 = xr[t], v1 = xr[t + 128], v2 = xr[t + 256];
    float s  = v0 + v1 + v2;
    float sq = v0*v0 + v1*v1 + v2*v2;

    __shared__ float sh[8];
    s  = warpReduceSum(s);
    sq = warpReduceSum(sq);
    const int w = t >> 5;
    if ((t & 31) == 0) { sh[w] = s; sh[w + 4] = sq; }
    __syncthreads();
    if (t < 32) {
        float a = (t < 4) ? sh[t]     : 0.f;
        float c = (t < 4) ? sh[t + 4] : 0.f;
        a = warpReduceSum(a);
        c = warpReduceSum(c);
        if (t == 0) { sh[0] = a; sh[1] = c; }
    }
    __syncthreads();

    const float mu   = sh[0] * (1.f / CDIM);
    const float var  = sh[1] * (1.f / CDIM) - mu * mu;
    const float rstd = rsqrtf(var + 1e-6f);

    #pragma unroll
    for (int e = 0; e < 3; e++) {
        const int i = t + e * 128;
        const float v = (e == 0) ? v0 : (e == 1) ? v1 : v2;
        dst[(size_t)row * CDIM + i] = __float2bfloat16((v - mu) * rstd * g[i] + b[i]);
    }
}

// ------------------------------------------------------- weight conversion
__global__ void cvt_kernel(const float* __restrict__ Wv,
                           const float* __restrict__ Wout,
                           const float* __restrict__ Wo,
                           const float* __restrict__ Wa)
{
    const int i = blockIdx.x * blockDim.x + threadIdx.x;
    if (i < CDIM * CDIM) {
        g_WvB[i]   = __float2bfloat16(Wv[i]);
        g_WoutB[i] = __float2bfloat16(Wout[i]);
    }
    if (i < CDIM * NPROJ) {
        const int k = i / NPROJ, c = i % NPROJ;
        float v = 0.f;
        if (c < 48)      v = Wo[k * 48 + c];
        else if (c < 72) v = Wa[k * 24 + (c - 48)];
        g_Wproj[i] = __float2bfloat16(v);
    }
}

// --------------------------- gemm0 body: g_value = g_fnorm @ g_WvB + bv ------
// BM=128 BN=128 BK=32, 3-stage cp.async, padded smem. 8 warps = 4(M) x 2(N).
__device__ __forceinline__ void gemm0_body(GemmSmem& sm, int bx, int by,
                                           const float* __restrict__ bias)
{
    const __nv_bfloat16* __restrict__ A  = g_fnorm;
    const __nv_bfloat16* __restrict__ Bm = g_WvB;

    const int bm   = bx * 128;
    const int bn   = by * 128;
    const int tid  = threadIdx.x;
    const int wid  = tid >> 5;
    const int lane = tid & 31;
    const int wm   = wid & 3;
    const int wn   = wid >> 2;

    const int a_r0 = tid >> 2,            a_o0 = (tid & 3) << 3;
    const int a_r1 = (tid + 256) >> 2;
    const int b_r0 = tid >> 4,            b_o0 = (tid & 15) << 3;
    const int b_r1 = (tid + 256) >> 4;

    auto load_stage = [&](int st, int k0) {
        cp_async16(&sm.sA[st][a_r0 * SAP + a_o0], A  + (size_t)(bm + a_r0) * CDIM + k0 + a_o0);
        cp_async16(&sm.sA[st][a_r1 * SAP + a_o0], A  + (size_t)(bm + a_r1) * CDIM + k0 + a_o0);
        cp_async16(&sm.sB[st][b_r0 * SBP + b_o0], Bm + (size_t)(k0 + b_r0) * CDIM + bn + b_o0);
        cp_async16(&sm.sB[st][b_r1 * SBP + b_o0], Bm + (size_t)(k0 + b_r1) * CDIM + bn + b_o0);
        cp_commit();
    };

    wmma::fragment<wmma::accumulator, 16, 16, 16, float> acc[2][4];
    #pragma unroll
    for (int i = 0; i < 2; i++)
        #pragma unroll
        for (int j = 0; j < 4; j++)
            wmma::fill_fragment(acc[i][j], 0.0f);

    load_stage(0, 0);
    load_stage(1, 32);

    const int KIT = CDIM / 32;   // 12
    for (int k = 0; k < KIT; k++) {
        cp_wait<1>();
        __syncthreads();
        const int st = k % 3;

        if (k + 2 < KIT) load_stage((k + 2) % 3, (k + 2) * 32);
        else             cp_commit();

        #pragma unroll
        for (int kk = 0; kk < 2; kk++) {
            wmma::fragment<wmma::matrix_a, 16, 16, 16, __nv_bfloat16, wmma::row_major> af[2];
            wmma::fragment<wmma::matrix_b, 16, 16, 16, __nv_bfloat16, wmma::row_major> bf;
            wmma::load_matrix_sync(af[0], &sm.sA[st][(wm * 32     ) * SAP + kk * 16], SAP);
            wmma::load_matrix_sync(af[1], &sm.sA[st][(wm * 32 + 16) * SAP + kk * 16], SAP);
            #pragma unroll
            for (int j = 0; j < 4; j++) {
                wmma::load_matrix_sync(bf, &sm.sB[st][(kk * 16) * SBP + wn * 64 + j * 16], SBP);
                wmma::mma_sync(acc[0][j], af[0], bf, acc[0][j]);
                wmma::mma_sync(acc[1][j], af[1], bf, acc[1][j]);
            }
        }
    }

    cp_wait<0>();
    __syncthreads();

    #pragma unroll
    for (int im = 0; im < 2; im++) {
        #pragma unroll
        for (int j = 0; j < 4; j++) {
            wmma::store_matrix_sync(sm.sC[wid], acc[im][j], 16, wmma::mem_row_major);
            __syncwarp();
            const int r  = lane >> 1;
            const int c0 = (lane & 1) << 3;
            const int gm = bm + wm * 32 + im * 16 + r;
            const int gn = bn + wn * 64 + j * 16 + c0;
            union { __nv_bfloat16 h[8]; uint4 u; } t;
            #pragma unroll
            for (int cc = 0; cc < 8; cc++)
                t.h[cc] = __float2bfloat16(sm.sC[wid][r * 16 + c0 + cc] + bias[gn + cc]);
            *(uint4*)&g_value[(size_t)gm * CDIM + gn] = t.u;
            __syncwarp();
        }
    }
}

// --------------------------- proj body: g_s = g_qnorm @ g_Wproj --------------
// BM=128 BN=80 BK=32, 2-stage cp.async, padded smem. 8 warps, each 16x80.
__device__ __forceinline__ void proj_body(ProjSmem& sm, int bx)
{
    const int bm   = bx * 128;
    const int tid  = threadIdx.x;
    const int wid  = tid >> 5;
    const int lane = tid & 31;

    const int a_r0 = tid >> 2,         a_o = (tid & 3) << 3;
    const int a_r1 = (tid + 256) >> 2;

    auto load_stage = [&](int st, int k0) {
        cp_async16(&sm.As[st][a_r0 * SAP + a_o], g_qnorm + (size_t)(bm + a_r0) * CDIM + k0 + a_o);
        cp_async16(&sm.As[st][a_r1 * SAP + a_o], g_qnorm + (size_t)(bm + a_r1) * CDIM + k0 + a_o);
        {
            const int c = tid;
            if (c < 320) {
                const int r = c / 10, o = (c % 10) << 3;
                cp_async16(&sm.Bs[st][r * SPP + o], g_Wproj + (size_t)(k0 + r) * NPROJ + o);
            }
            const int c2 = tid + 256;
            if (c2 < 320) {
                const int r = c2 / 10, o = (c2 % 10) << 3;
                cp_async16(&sm.Bs[st][r * SPP + o], g_Wproj + (size_t)(k0 + r) * NPROJ + o);
            }
        }
        cp_commit();
    };

    wmma::fragment<wmma::accumulator, 16, 16, 16, float> acc[5];
    #pragma unroll
    for (int j = 0; j < 5; j++) wmma::fill_fragment(acc[j], 0.0f);

    load_stage(0, 0);
    const int KIT = CDIM / 32;   // 12
    for (int k = 0; k < KIT; k++) {
        cp_wait<0>();
        __syncthreads();
        const int st = k & 1;
        if (k + 1 < KIT) load_stage((k + 1) & 1, (k + 1) * 32);

        #pragma unroll
        for (int kk = 0; kk < 2; kk++) {
            wmma::fragment<wmma::matrix_a, 16, 16, 16, __nv_bfloat16, wmma::row_major> af;
            wmma::fragment<wmma::matrix_b, 16, 16, 16, __nv_bfloat16, wmma::row_major> bf;
            wmma::load_matrix_sync(af, &sm.As[st][(wid * 16) * SAP + kk * 16], SAP);
            #pragma unroll
            for (int j = 0; j < 5; j++) {
                wmma::load_matrix_sync(bf, &sm.Bs[st][(kk * 16) * SPP + j * 16], SPP);
                wmma::mma_sync(acc[j], af, bf, acc[j]);
            }
        }
    }

    cp_wait<0>();
    __syncthreads();

    #pragma unroll
    for (int j = 0; j < 5; j++) {
        wmma::store_matrix_sync(sm.Cs[wid], acc[j], 16, wmma::mem_row_major);
        __syncwarp();
        const int r  = lane >> 1;
        const int c0 = (lane & 1) << 3;
        const int gm = bm + wid * 16 + r;
        const int gn = j * 16 + c0;
        #pragma unroll
        for (int cc = 0; cc < 8; cc++)
            g_s[(size_t)gm * NPROJ + gn + cc] = sm.Cs[wid][r * 16 + c0 + cc];
        __syncwarp();
    }
}

// ------------------------- merged mid kernel: gemm0 tiles + proj tiles -------
// grid (128, 4): y in [0,3) -> gemm0 tile (bm=x*128, bn=y*128); y==3 -> proj tile.
__global__ __launch_bounds__(256)
void mid_kernel(const float* __restrict__ bv)
{
    __shared__ MidSmem sm;
    if (blockIdx.y < 3) gemm0_body(sm.g, blockIdx.x, blockIdx.y, bv);
    else                proj_body(sm.p, blockIdx.x);
}

// --------------------------- final GEMM: out = query + gamma*(samp@Wout+bout)
__global__ __launch_bounds__(256)
void gemm1_kernel(const float* __restrict__ bias,
                  const float* __restrict__ query,
                  const float* __restrict__ gamma,
                  float* __restrict__ out)
{
    const __nv_bfloat16* __restrict__ A  = g_samp;
    const __nv_bfloat16* __restrict__ Bm = g_WoutB;

    __shared__ GemmSmem sm;

    const int bm   = blockIdx.x * 128;
    const int bn   = blockIdx.y * 128;
    const int tid  = threadIdx.x;
    const int wid  = tid >> 5;
    const int lane = tid & 31;
    const int wm   = wid & 3;
    const int wn   = wid >> 2;

    const int a_r0 = tid >> 2,            a_o0 = (tid & 3) << 3;
    const int a_r1 = (tid + 256) >> 2;
    const int b_r0 = tid >> 4,            b_o0 = (tid & 15) << 3;
    const int b_r1 = (tid + 256) >> 4;

    auto load_stage = [&](int st, int k0) {
        cp_async16(&sm.sA[st][a_r0 * SAP + a_o0], A  + (size_t)(bm + a_r0) * CDIM + k0 + a_o0);
        cp_async16(&sm.sA[st][a_r1 * SAP + a_o0], A  + (size_t)(bm + a_r1) * CDIM + k0 + a_o0);
        cp_async16(&sm.sB[st][b_r0 * SBP + b_o0], Bm + (size_t)(k0 + b_r0) * CDIM + bn + b_o0);
        cp_async16(&sm.sB[st][b_r1 * SBP + b_o0], Bm + (size_t)(k0 + b_r1) * CDIM + bn + b_o0);
        cp_commit();
    };

    wmma::fragment<wmma::accumulator, 16, 16, 16, float> acc[2][4];
    #pragma unroll
    for (int i = 0; i < 2; i++)
        #pragma unroll
        for (int j = 0; j < 4; j++)
            wmma::fill_fragment(acc[i][j], 0.0f);

    load_stage(0, 0);
    load_stage(1, 32);

    const int KIT = CDIM / 32;   // 12
    for (int k = 0; k < KIT; k++) {
        cp_wait<1>();
        __syncthreads();
        const int st = k % 3;

        if (k + 2 < KIT) load_stage((k + 2) % 3, (k + 2) * 32);
        else             cp_commit();

        #pragma unroll
        for (int kk = 0; kk < 2; kk++) {
            wmma::fragment<wmma::matrix_a, 16, 16, 16, __nv_bfloat16, wmma::row_major> af[2];
            wmma::fragment<wmma::matrix_b, 16, 16, 16, __nv_bfloat16, wmma::row_major> bf;
            wmma::load_matrix_sync(af[0], &sm.sA[st][(wm * 32     ) * SAP + kk * 16], SAP);
            wmma::load_matrix_sync(af[1], &sm.sA[st][(wm * 32 + 16) * SAP + kk * 16], SAP);
            #pragma unroll
            for (int j = 0; j < 4; j++) {
                wmma::load_matrix_sync(bf, &sm.sB[st][(kk * 16) * SBP + wn * 64 + j * 16], SBP);
                wmma::mma_sync(acc[0][j], af[0], bf, acc[0][j]);
                wmma::mma_sync(acc[1][j], af[1], bf, acc[1][j]);
            }
        }
    }

    cp_wait<0>();
    __syncthreads();

    #pragma unroll
    for (int im = 0; im < 2; im++) {
        #pragma unroll
        for (int j = 0; j < 4; j++) {
            wmma::store_matrix_sync(sm.sC[wid], acc[im][j], 16, wmma::mem_row_major);
            __syncwarp();
            const int r  = lane >> 1;
            const int c0 = (lane & 1) << 3;
            const int gm = bm + wm * 32 + im * 16 + r;
            const int gn = bn + wn * 64 + j * 16 + c0;
            const size_t base = (size_t)gm * CDIM + gn;
            float4 q0 = *(const float4*)&query[base];
            float4 q1 = *(const float4*)&query[base + 4];
            float4 o0, o1;
            o0.x = q0.x + gamma[gn+0] * (sm.sC[wid][r*16+c0+0] + bias[gn+0]);
            o0.y = q0.y + gamma[gn+1] * (sm.sC[wid][r*16+c0+1] + bias[gn+1]);
            o0.z = q0.z + gamma[gn+2] * (sm.sC[wid][r*16+c0+2] + bias[gn+2]);
            o0.w = q0.w + gamma[gn+3] * (sm.sC[wid][r*16+c0+3] + bias[gn+3]);
            o1.x = q1.x + gamma[gn+4] * (sm.sC[wid][r*16+c0+4] + bias[gn+4]);
            o1.y = q1.y + gamma[gn+5] * (sm.sC[wid][r*16+c0+5] + bias[gn+5]);
            o1.z = q1.z + gamma[gn+6] * (sm.sC[wid][r*16+c0+6] + bias[gn+6]);
            o1.w = q1.w + gamma[gn+7] * (sm.sC[wid][r*16+c0+7] + bias[gn+7]);
            *(float4*)&out[base]     = o0;
            *(float4*)&out[base + 4] = o1;
            __syncwarp();
        }
    }
}

// ------------------------------ sampling (softmax + locations fused) --------
// blockDim (32,8): lane = uint (2 channels), y-slot = (row,head) unit
__global__ __launch_bounds__(256)
void sample_kernel(const float* __restrict__ bo,
                   const float* __restrict__ ba,
                   const float* __restrict__ refp)
{
    const int lane = threadIdx.x;                    // 0..31, 2 channels each
    const int u = blockIdx.x * 8 + threadIdx.y;      // 0 .. MROW*NH-1
    const int h   = u % NH;
    const int row = u / NH;
    const int b   = row >> 12;

    const float rx = refp[(size_t)row * 2 + 0] * 64.f - 0.5f;
    const float ry = refp[(size_t)row * 2 + 1] * 64.f - 0.5f;
    const float* srow = g_s + (size_t)row * NPROJ;

    // softmax over the head's 4 attention logits (redundant per lane; L1 broadcast)
    float aw[NP]; float m = -1e30f;
    #pragma unroll
    for (int p = 0; p < NP; p++) {
        aw[p] = srow[48 + h * NP + p] + ba[h * NP + p];
        m = fmaxf(m, aw[p]);
    }
    float ssum = 0.f;
    #pragma unroll
    for (int p = 0; p < NP; p++) { aw[p] = __expf(aw[p] - m); ssum += aw[p]; }
    const float inv = 1.f / ssum;

    // uint view: each lane handles channels {2*lane, 2*lane+1} of this head
    const unsigned int* __restrict__ vb =
        (const unsigned int*)(g_value + (size_t)b * LV * CDIM + h * DH) + lane;
    float acc0 = 0.f, acc1 = 0.f;

    #pragma unroll
    for (int p = 0; p < NP; p++) {
        // loc*64 - 0.5 == ref*64 + offset - 0.5 (W == H == 64 cancels the /64)
        const float x = rx + srow[h * 8 + p * 2 + 0] + bo[h * 8 + p * 2 + 0];
        const float y = ry + srow[h * 8 + p * 2 + 1] + bo[h * 8 + p * 2 + 1];
        const float w = aw[p] * inv;
        const float x0f = floorf(x), y0f = floorf(y);
        const int   x0 = (int)x0f,  y0 = (int)y0f;
        const float wx = x - x0f,   wy = y - y0f;

        const bool xin0 = (x0 >= 0) & (x0 < WL), xin1 = (x0+1 >= 0) & (x0+1 < WL);
        const bool yin0 = (y0 >= 0) & (y0 < HL), yin1 = (y0+1 >= 0) & (y0+1 < HL);

        #pragma unroll
        for (int c = 0; c < 4; c++) {
            const int  xi = x0 + (c & 1),  yi = y0 + (c >> 1);
            const bool ok = (c & 1 ? xin1 : xin0) & (c >> 1 ? yin1 : yin0);
            if (ok) {
                const float cw = ((c & 1) ? wx : 1.f - wx) * ((c >> 1) ? wy : 1.f - wy) * w;
                const unsigned int pk = vb[(size_t)(yi * WL + xi) * (CDIM / 2)];
                __nv_bfloat162 v2 = *(const __nv_bfloat162*)&pk;
                acc0 += cw * __bfloat162float(v2.x);
                acc1 += cw * __bfloat162float(v2.y);
            }
        }
    }
    __nv_bfloat162 o; o.x = __float2bfloat16(acc0); o.y = __float2bfloat16(acc1);
    *(__nv_bfloat162*)&g_samp[(size_t)row * CDIM + h * DH + lane * 2] = o;
}

// ------------------------------------------------------------------- launch
extern "C" void kernel_launch(void* const* d_in, const int* in_sizes, int n_in,
                              void* d_out, int out_size)
{
    const float* query  = (const float*)d_in[0];
    const float* refp   = (const float*)d_in[1];
    const float* feat   = (const float*)d_in[2];
    const float* ln_q_g = (const float*)d_in[5];
    const float* ln_q_b = (const float*)d_in[6];
    const float* ln_f_g = (const float*)d_in[7];
    const float* ln_f_b = (const float*)d_in[8];
    const float* gamma  = (const float*)d_in[9];
    const float* Wv     = (const float*)d_in[10];
    const float* bv     = (const float*)d_in[11];
    const float* bo     = (const float*)d_in[13];
    const float* Wo     = (const float*)d_in[12];
    const float* Wa     = (const float*)d_in[14];
    const float* ba     = (const float*)d_in[15];
    const float* Wout   = (const float*)d_in[16];
    const float* bout   = (const float*)d_in[17];
    float* out = (float*)d_out;

    ln_kernel<<<2 * MROW, 128>>>(feat, query, ln_f_g, ln_f_b, ln_q_g, ln_q_b);
    cvt_kernel<<<(CDIM * CDIM + 255) / 256, 256>>>(Wv, Wout, Wo, Wa);

    mid_kernel<<<dim3(MROW / 128, 4), 256>>>(bv);                 // gemm0 + proj
    sample_kernel<<<(MROW * NH) / 8, dim3(32, 8)>>>(bo, ba, refp);
    gemm1_kernel<<<dim3(MROW / 128, CDIM / 128), 256>>>(bout, query, gamma, out);
}

// round 14
// speedup vs baseline: 3.3369x; 1.1087x over previous
#include <cuda_runtime.h>
#include <cuda_bf16.h>
#include <mma.h>
#include <cstdint>

using namespace nvcuda;

#define BATCH 4
#define LQ    4096
#define CDIM  384
#define NH    6
#define NP    4
#define DH    64
#define HL    64
#define WL    64
#define LV    (HL*WL)          // 4096
#define MROW  (BATCH*LQ)       // 16384
#define NPROJ 80               // 48 offsets + 24 attn logits + 8 pad

// padded shared strides (conflict-free LDSM phases; all multiples of 16B)
#define SAP   40               // A tile ldm (elems): 80B row stride
#define SBP   136              // B tile ldm (elems): 272B row stride
#define SPP   88               // proj B tile ldm (elems): 176B row stride

// ---------------- scratch (static device globals) ---------------------------
__device__ __nv_bfloat16 g_fnorm[MROW * CDIM];     // LN(feat)  bf16
__device__ __nv_bfloat16 g_qnorm[MROW * CDIM];     // LN(query) bf16
__device__ __nv_bfloat16 g_value[MROW * CDIM];     // value = fnorm@Wv+bv (bf16)
__device__ __nv_bfloat16 g_samp [MROW * CDIM];     // sampled attention (bf16)
__device__ float         g_s    [MROW * NPROJ];    // raw proj logits (no bias)
__device__ __nv_bfloat16 g_WvB  [CDIM * CDIM];
__device__ __nv_bfloat16 g_WoutB[CDIM * CDIM];
__device__ __nv_bfloat16 g_Wproj[CDIM * NPROJ];    // [Wo | Wa | 0pad]

// ---------------------------------------------------------------- cp.async
__device__ __forceinline__ void cp_async16(void* smem, const void* gmem) {
    unsigned int s = (unsigned int)__cvta_generic_to_shared(smem);
    asm volatile("cp.async.cg.shared.global [%0], [%1], 16;\n" :: "r"(s), "l"(gmem));
}
__device__ __forceinline__ void cp_commit() {
    asm volatile("cp.async.commit_group;\n");
}
template<int N> __device__ __forceinline__ void cp_wait() {
    asm volatile("cp.async.wait_group %0;\n" :: "n"(N));
}

__device__ __forceinline__ float warpReduceSum(float v) {
    #pragma unroll
    for (int o = 16; o > 0; o >>= 1) v += __shfl_xor_sync(0xffffffffu, v, o);
    return v;
}

// ---------------------------------------------------------- shared layouts
struct GemmSmem {
    __nv_bfloat16 sA[3][128 * SAP];
    __nv_bfloat16 sB[3][32 * SBP];
    float         sC[8][256];
};
struct ProjSmem {
    __nv_bfloat16 As[2][128 * SAP];
    __nv_bfloat16 Bs[2][32 * SPP];
    float         Cs[8][256];
};
union MidSmem { GemmSmem g; ProjSmem p; };

// ------------------------------------------------------------- layernorm
// one merged launch: blocks [0, MROW) -> feat, [MROW, 2*MROW) -> query
__global__ void ln_kernel(const float* __restrict__ feat,
                          const float* __restrict__ query,
                          const float* __restrict__ gf, const float* __restrict__ bf_,
                          const float* __restrict__ gq, const float* __restrict__ bq)
{
    const bool isq = blockIdx.x >= MROW;
    const int row  = isq ? (blockIdx.x - MROW) : blockIdx.x;
    const float* __restrict__ x = isq ? query : feat;
    const float* __restrict__ g = isq ? gq : gf;
    const float* __restrict__ b = isq ? bq : bf_;
    __nv_bfloat16* dst = isq ? g_qnorm : g_fnorm;

    const float* xr = x + (size_t)row * CDIM;
    const int t = threadIdx.x;

    float v0 = xr[t], v1 = xr[t + 128], v2 = xr[t + 256];
    float s  = v0 + v1 + v2;
    float sq = v0*v0 + v1*v1 + v2*v2;

    __shared__ float sh[8];
    s  = warpReduceSum(s);
    sq = warpReduceSum(sq);
    const int w = t >> 5;
    if ((t & 31) == 0) { sh[w] = s; sh[w + 4] = sq; }
    __syncthreads();
    if (t < 32) {
        float a = (t < 4) ? sh[t]     : 0.f;
        float c = (t < 4) ? sh[t + 4] : 0.f;
        a = warpReduceSum(a);
        c = warpReduceSum(c);
        if (t == 0) { sh[0] = a; sh[1] = c; }
    }
    __syncthreads();

    const float mu   = sh[0] * (1.f / CDIM);
    const float var  = sh[1] * (1.f / CDIM) - mu * mu;
    const float rstd = rsqrtf(var + 1e-6f);

    #pragma unroll
    for (int e = 0; e < 3; e++) {
        const int i = t + e * 128;
        const float v = (e == 0) ? v0 : (e == 1) ? v1 : v2;
        dst[(size_t)row * CDIM + i] = __float2bfloat16((v - mu) * rstd * g[i] + b[i]);
    }
}

// ------------------------------------------------------- weight conversion
__global__ void cvt_kernel(const float* __restrict__ Wv,
                           const float* __restrict__ Wout,
                           const float* __restrict__ Wo,
                           const float* __restrict__ Wa)
{
    const int i = blockIdx.x * blockDim.x + threadIdx.x;
    if (i < CDIM * CDIM) {
        g_WvB[i]   = __float2bfloat16(Wv[i]);
        g_WoutB[i] = __float2bfloat16(Wout[i]);
    }
    if (i < CDIM * NPROJ) {
        const int k = i / NPROJ, c = i % NPROJ;
        float v = 0.f;
        if (c < 48)      v = Wo[k * 48 + c];
        else if (c < 72) v = Wa[k * 24 + (c - 48)];
        g_Wproj[i] = __float2bfloat16(v);
    }
}

// --------------------------- gemm0 body: g_value = g_fnorm @ g_WvB + bv ------
// BM=128 BN=128 BK=32, 3-stage cp.async, padded smem. 8 warps = 4(M) x 2(N).
__device__ __forceinline__ void gemm0_body(GemmSmem& sm, int bx, int by,
                                           const float* __restrict__ bias)
{
    const __nv_bfloat16* __restrict__ A  = g_fnorm;
    const __nv_bfloat16* __restrict__ Bm = g_WvB;

    const int bm   = bx * 128;
    const int bn   = by * 128;
    const int tid  = threadIdx.x;
    const int wid  = tid >> 5;
    const int lane = tid & 31;
    const int wm   = wid & 3;
    const int wn   = wid >> 2;

    const int a_r0 = tid >> 2,            a_o0 = (tid & 3) << 3;
    const int a_r1 = (tid + 256) >> 2;
    const int b_r0 = tid >> 4,            b_o0 = (tid & 15) << 3;
    const int b_r1 = (tid + 256) >> 4;

    auto load_stage = [&](int st, int k0) {
        cp_async16(&sm.sA[st][a_r0 * SAP + a_o0], A  + (size_t)(bm + a_r0) * CDIM + k0 + a_o0);
        cp_async16(&sm.sA[st][a_r1 * SAP + a_o0], A  + (size_t)(bm + a_r1) * CDIM + k0 + a_o0);
        cp_async16(&sm.sB[st][b_r0 * SBP + b_o0], Bm + (size_t)(k0 + b_r0) * CDIM + bn + b_o0);
        cp_async16(&sm.sB[st][b_r1 * SBP + b_o0], Bm + (size_t)(k0 + b_r1) * CDIM + bn + b_o0);
        cp_commit();
    };

    wmma::fragment<wmma::accumulator, 16, 16, 16, float> acc[2][4];
    #pragma unroll
    for (int i = 0; i < 2; i++)
        #pragma unroll
        for (int j = 0; j < 4; j++)
            wmma::fill_fragment(acc[i][j], 0.0f);

    load_stage(0, 0);
    load_stage(1, 32);

    const int KIT = CDIM / 32;   // 12
    for (int k = 0; k < KIT; k++) {
        cp_wait<1>();
        __syncthreads();
        const int st = k % 3;

        if (k + 2 < KIT) load_stage((k + 2) % 3, (k + 2) * 32);
        else             cp_commit();

        #pragma unroll
        for (int kk = 0; kk < 2; kk++) {
            wmma::fragment<wmma::matrix_a, 16, 16, 16, __nv_bfloat16, wmma::row_major> af[2];
            wmma::fragment<wmma::matrix_b, 16, 16, 16, __nv_bfloat16, wmma::row_major> bf;
            wmma::load_matrix_sync(af[0], &sm.sA[st][(wm * 32     ) * SAP + kk * 16], SAP);
            wmma::load_matrix_sync(af[1], &sm.sA[st][(wm * 32 + 16) * SAP + kk * 16], SAP);
            #pragma unroll
            for (int j = 0; j < 4; j++) {
                wmma::load_matrix_sync(bf, &sm.sB[st][(kk * 16) * SBP + wn * 64 + j * 16], SBP);
                wmma::mma_sync(acc[0][j], af[0], bf, acc[0][j]);
                wmma::mma_sync(acc[1][j], af[1], bf, acc[1][j]);
            }
        }
    }

    cp_wait<0>();
    __syncthreads();

    #pragma unroll
    for (int im = 0; im < 2; im++) {
        #pragma unroll
        for (int j = 0; j < 4; j++) {
            wmma::store_matrix_sync(sm.sC[wid], acc[im][j], 16, wmma::mem_row_major);
            __syncwarp();
            const int r  = lane >> 1;
            const int c0 = (lane & 1) << 3;
            const int gm = bm + wm * 32 + im * 16 + r;
            const int gn = bn + wn * 64 + j * 16 + c0;
            union { __nv_bfloat16 h[8]; uint4 u; } t;
            #pragma unroll
            for (int cc = 0; cc < 8; cc++)
                t.h[cc] = __float2bfloat16(sm.sC[wid][r * 16 + c0 + cc] + bias[gn + cc]);
            *(uint4*)&g_value[(size_t)gm * CDIM + gn] = t.u;
            __syncwarp();
        }
    }
}

// --------------------------- proj body: g_s = g_qnorm @ g_Wproj --------------
// BM=128 BN=80 BK=32, 2-stage cp.async, padded smem. 8 warps, each 16x80.
__device__ __forceinline__ void proj_body(ProjSmem& sm, int bx)
{
    const int bm   = bx * 128;
    const int tid  = threadIdx.x;
    const int wid  = tid >> 5;
    const int lane = tid & 31;

    const int a_r0 = tid >> 2,         a_o = (tid & 3) << 3;
    const int a_r1 = (tid + 256) >> 2;

    auto load_stage = [&](int st, int k0) {
        cp_async16(&sm.As[st][a_r0 * SAP + a_o], g_qnorm + (size_t)(bm + a_r0) * CDIM + k0 + a_o);
        cp_async16(&sm.As[st][a_r1 * SAP + a_o], g_qnorm + (size_t)(bm + a_r1) * CDIM + k0 + a_o);
        {
            const int c = tid;
            if (c < 320) {
                const int r = c / 10, o = (c % 10) << 3;
                cp_async16(&sm.Bs[st][r * SPP + o], g_Wproj + (size_t)(k0 + r) * NPROJ + o);
            }
            const int c2 = tid + 256;
            if (c2 < 320) {
                const int r = c2 / 10, o = (c2 % 10) << 3;
                cp_async16(&sm.Bs[st][r * SPP + o], g_Wproj + (size_t)(k0 + r) * NPROJ + o);
            }
        }
        cp_commit();
    };

    wmma::fragment<wmma::accumulator, 16, 16, 16, float> acc[5];
    #pragma unroll
    for (int j = 0; j < 5; j++) wmma::fill_fragment(acc[j], 0.0f);

    load_stage(0, 0);
    const int KIT = CDIM / 32;   // 12
    for (int k = 0; k < KIT; k++) {
        cp_wait<0>();
        __syncthreads();
        const int st = k & 1;
        if (k + 1 < KIT) load_stage((k + 1) & 1, (k + 1) * 32);

        #pragma unroll
        for (int kk = 0; kk < 2; kk++) {
            wmma::fragment<wmma::matrix_a, 16, 16, 16, __nv_bfloat16, wmma::row_major> af;
            wmma::fragment<wmma::matrix_b, 16, 16, 16, __nv_bfloat16, wmma::row_major> bf;
            wmma::load_matrix_sync(af, &sm.As[st][(wid * 16) * SAP + kk * 16], SAP);
            #pragma unroll
            for (int j = 0; j < 5; j++) {
                wmma::load_matrix_sync(bf, &sm.Bs[st][(kk * 16) * SPP + j * 16], SPP);
                wmma::mma_sync(acc[j], af, bf, acc[j]);
            }
        }
    }

    cp_wait<0>();
    __syncthreads();

    #pragma unroll
    for (int j = 0; j < 5; j++) {
        wmma::store_matrix_sync(sm.Cs[wid], acc[j], 16, wmma::mem_row_major);
        __syncwarp();
        const int r  = lane >> 1;
        const int c0 = (lane & 1) << 3;
        const int gm = bm + wid * 16 + r;
        const int gn = j * 16 + c0;
        #pragma unroll
        for (int cc = 0; cc < 8; cc++)
            g_s[(size_t)gm * NPROJ + gn + cc] = sm.Cs[wid][r * 16 + c0 + cc];
        __syncwarp();
    }
}

// ------------------------- merged mid kernel: gemm0 tiles + proj tiles -------
// grid (128, 4): y in [0,3) -> gemm0 tile (bm=x*128, bn=y*128); y==3 -> proj tile.
__global__ __launch_bounds__(256)
void mid_kernel(const float* __restrict__ bv)
{
    __shared__ MidSmem sm;
    if (blockIdx.y < 3) gemm0_body(sm.g, blockIdx.x, blockIdx.y, bv);
    else                proj_body(sm.p, blockIdx.x);
}

// --------------------------- final GEMM: out = query + gamma*(samp@Wout+bout)
__global__ __launch_bounds__(256)
void gemm1_kernel(const float* __restrict__ bias,
                  const float* __restrict__ query,
                  const float* __restrict__ gamma,
                  float* __restrict__ out)
{
    const __nv_bfloat16* __restrict__ A  = g_samp;
    const __nv_bfloat16* __restrict__ Bm = g_WoutB;

    __shared__ GemmSmem sm;

    const int bm   = blockIdx.x * 128;
    const int bn   = blockIdx.y * 128;
    const int tid  = threadIdx.x;
    const int wid  = tid >> 5;
    const int lane = tid & 31;
    const int wm   = wid & 3;
    const int wn   = wid >> 2;

    const int a_r0 = tid >> 2,            a_o0 = (tid & 3) << 3;
    const int a_r1 = (tid + 256) >> 2;
    const int b_r0 = tid >> 4,            b_o0 = (tid & 15) << 3;
    const int b_r1 = (tid + 256) >> 4;

    auto load_stage = [&](int st, int k0) {
        cp_async16(&sm.sA[st][a_r0 * SAP + a_o0], A  + (size_t)(bm + a_r0) * CDIM + k0 + a_o0);
        cp_async16(&sm.sA[st][a_r1 * SAP + a_o0], A  + (size_t)(bm + a_r1) * CDIM + k0 + a_o0);
        cp_async16(&sm.sB[st][b_r0 * SBP + b_o0], Bm + (size_t)(k0 + b_r0) * CDIM + bn + b_o0);
        cp_async16(&sm.sB[st][b_r1 * SBP + b_o0], Bm + (size_t)(k0 + b_r1) * CDIM + bn + b_o0);
        cp_commit();
    };

    wmma::fragment<wmma::accumulator, 16, 16, 16, float> acc[2][4];
    #pragma unroll
    for (int i = 0; i < 2; i++)
        #pragma unroll
        for (int j = 0; j < 4; j++)
            wmma::fill_fragment(acc[i][j], 0.0f);

    load_stage(0, 0);
    load_stage(1, 32);

    const int KIT = CDIM / 32;   // 12
    for (int k = 0; k < KIT; k++) {
        cp_wait<1>();
        __syncthreads();
        const int st = k % 3;

        if (k + 2 < KIT) load_stage((k + 2) % 3, (k + 2) * 32);
        else             cp_commit();

        #pragma unroll
        for (int kk = 0; kk < 2; kk++) {
            wmma::fragment<wmma::matrix_a, 16, 16, 16, __nv_bfloat16, wmma::row_major> af[2];
            wmma::fragment<wmma::matrix_b, 16, 16, 16, __nv_bfloat16, wmma::row_major> bf;
            wmma::load_matrix_sync(af[0], &sm.sA[st][(wm * 32     ) * SAP + kk * 16], SAP);
            wmma::load_matrix_sync(af[1], &sm.sA[st][(wm * 32 + 16) * SAP + kk * 16], SAP);
            #pragma unroll
            for (int j = 0; j < 4; j++) {
                wmma::load_matrix_sync(bf, &sm.sB[st][(kk * 16) * SBP + wn * 64 + j * 16], SBP);
                wmma::mma_sync(acc[0][j], af[0], bf, acc[0][j]);
                wmma::mma_sync(acc[1][j], af[1], bf, acc[1][j]);
            }
        }
    }

    cp_wait<0>();
    __syncthreads();

    #pragma unroll
    for (int im = 0; im < 2; im++) {
        #pragma unroll
        for (int j = 0; j < 4; j++) {
            wmma::store_matrix_sync(sm.sC[wid], acc[im][j], 16, wmma::mem_row_major);
            __syncwarp();
            const int r  = lane >> 1;
            const int c0 = (lane & 1) << 3;
            const int gm = bm + wm * 32 + im * 16 + r;
            const int gn = bn + wn * 64 + j * 16 + c0;
            const size_t base = (size_t)gm * CDIM + gn;
            float4 q0 = *(const float4*)&query[base];
            float4 q1 = *(const float4*)&query[base + 4];
            float4 o0, o1;
            o0.x = q0.x + gamma[gn+0] * (sm.sC[wid][r*16+c0+0] + bias[gn+0]);
            o0.y = q0.y + gamma[gn+1] * (sm.sC[wid][r*16+c0+1] + bias[gn+1]);
            o0.z = q0.z + gamma[gn+2] * (sm.sC[wid][r*16+c0+2] + bias[gn+2]);
            o0.w = q0.w + gamma[gn+3] * (sm.sC[wid][r*16+c0+3] + bias[gn+3]);
            o1.x = q1.x + gamma[gn+4] * (sm.sC[wid][r*16+c0+4] + bias[gn+4]);
            o1.y = q1.y + gamma[gn+5] * (sm.sC[wid][r*16+c0+5] + bias[gn+5]);
            o1.z = q1.z + gamma[gn+6] * (sm.sC[wid][r*16+c0+6] + bias[gn+6]);
            o1.w = q1.w + gamma[gn+7] * (sm.sC[wid][r*16+c0+7] + bias[gn+7]);
            *(float4*)&out[base]     = o0;
            *(float4*)&out[base + 4] = o1;
            __syncwarp();
        }
    }
}

// ------------------------------ sampling (softmax + locations fused) --------
// blockDim (16,16): lane = uint2 (4 channels), y-slot = (row,head) unit.
// Fewer, wider gathers: halves instruction streams vs the 2-channel version.
__global__ __launch_bounds__(256)
void sample_kernel(const float* __restrict__ bo,
                   const float* __restrict__ ba,
                   const float* __restrict__ refp)
{
    const int lane = threadIdx.x;                    // 0..15, 4 channels each
    const int u = blockIdx.x * 16 + threadIdx.y;     // 0 .. MROW*NH-1
    const int h   = u % NH;
    const int row = u / NH;
    const int b   = row >> 12;

    const float rx = refp[(size_t)row * 2 + 0] * 64.f - 0.5f;
    const float ry = refp[(size_t)row * 2 + 1] * 64.f - 0.5f;
    const float* srow = g_s + (size_t)row * NPROJ;

    // softmax over the head's 4 attention logits
    float aw[NP]; float m = -1e30f;
    #pragma unroll
    for (int p = 0; p < NP; p++) {
        aw[p] = srow[48 + h * NP + p] + ba[h * NP + p];
        m = fmaxf(m, aw[p]);
    }
    float ssum = 0.f;
    #pragma unroll
    for (int p = 0; p < NP; p++) { aw[p] = __expf(aw[p] - m); ssum += aw[p]; }
    const float inv = 1.f / ssum;

    // uint2 view: each lane handles channels {4*lane .. 4*lane+3} of this head
    const uint2* __restrict__ vb =
        (const uint2*)(g_value + (size_t)b * LV * CDIM + h * DH) + lane;
    float acc0 = 0.f, acc1 = 0.f, acc2 = 0.f, acc3 = 0.f;

    #pragma unroll
    for (int p = 0; p < NP; p++) {
        // loc*64 - 0.5 == ref*64 + offset - 0.5 (W == H == 64 cancels the /64)
        const float x = rx + srow[h * 8 + p * 2 + 0] + bo[h * 8 + p * 2 + 0];
        const float y = ry + srow[h * 8 + p * 2 + 1] + bo[h * 8 + p * 2 + 1];
        const float w = aw[p] * inv;
        const float x0f = floorf(x), y0f = floorf(y);
        const int   x0 = (int)x0f,  y0 = (int)y0f;
        const float wx = x - x0f,   wy = y - y0f;

        const bool xin0 = (x0 >= 0) & (x0 < WL), xin1 = (x0+1 >= 0) & (x0+1 < WL);
        const bool yin0 = (y0 >= 0) & (y0 < HL), yin1 = (y0+1 >= 0) & (y0+1 < HL);

        #pragma unroll
        for (int c = 0; c < 4; c++) {
            const int  xi = x0 + (c & 1),  yi = y0 + (c >> 1);
            const bool ok = (c & 1 ? xin1 : xin0) & (c >> 1 ? yin1 : yin0);
            if (ok) {
                const float cw = ((c & 1) ? wx : 1.f - wx) * ((c >> 1) ? wy : 1.f - wy) * w;
                const unsigned int off = (unsigned int)(yi * WL + xi) * (CDIM / 4);
                const uint2 pk = vb[off];
                const __nv_bfloat162 vlo = *(const __nv_bfloat162*)&pk.x;
                const __nv_bfloat162 vhi = *(const __nv_bfloat162*)&pk.y;
                acc0 += cw * __bfloat162float(vlo.x);
                acc1 += cw * __bfloat162float(vlo.y);
                acc2 += cw * __bfloat162float(vhi.x);
                acc3 += cw * __bfloat162float(vhi.y);
            }
        }
    }
    union { __nv_bfloat16 h4[4]; uint2 u2; } o;
    o.h4[0] = __float2bfloat16(acc0);
    o.h4[1] = __float2bfloat16(acc1);
    o.h4[2] = __float2bfloat16(acc2);
    o.h4[3] = __float2bfloat16(acc3);
    *(uint2*)&g_samp[(size_t)row * CDIM + h * DH + lane * 4] = o.u2;
}

// ------------------------------------------------------------------- launch
extern "C" void kernel_launch(void* const* d_in, const int* in_sizes, int n_in,
                              void* d_out, int out_size)
{
    const float* query  = (const float*)d_in[0];
    const float* refp   = (const float*)d_in[1];
    const float* feat   = (const float*)d_in[2];
    const float* ln_q_g = (const float*)d_in[5];
    const float* ln_q_b = (const float*)d_in[6];
    const float* ln_f_g = (const float*)d_in[7];
    const float* ln_f_b = (const float*)d_in[8];
    const float* gamma  = (const float*)d_in[9];
    const float* Wv     = (const float*)d_in[10];
    const float* bv     = (const float*)d_in[11];
    const float* Wo     = (const float*)d_in[12];
    const float* bo     = (const float*)d_in[13];
    const float* Wa     = (const float*)d_in[14];
    const float* ba     = (const float*)d_in[15];
    const float* Wout   = (const float*)d_in[16];
    const float* bout   = (const float*)d_in[17];
    float* out = (float*)d_out;

    ln_kernel<<<2 * MROW, 128>>>(feat, query, ln_f_g, ln_f_b, ln_q_g, ln_q_b);
    cvt_kernel<<<(CDIM * CDIM + 255) / 256, 256>>>(Wv, Wout, Wo, Wa);

    mid_kernel<<<dim3(MROW / 128, 4), 256>>>(bv);                 // gemm0 + proj
    sample_kernel<<<(MROW * NH) / 16, dim3(16, 16)>>>(bo, ba, refp);
    gemm1_kernel<<<dim3(MROW / 128, CDIM / 128), 256>>>(bout, query, gamma, out);
}

// round 15
// speedup vs baseline: 3.3735x; 1.0110x over previous
#include <cuda_runtime.h>
#include <cuda_bf16.h>
#include <mma.h>
#include <cstdint>

using namespace nvcuda;

#define BATCH 4
#define LQ    4096
#define CDIM  384
#define NH    6
#define NP    4
#define DH    64
#define HL    64
#define WL    64
#define LV    (HL*WL)          // 4096
#define MROW  (BATCH*LQ)       // 16384
#define NPROJ 80               // 48 offsets + 24 attn logits + 8 pad

// padded shared strides (conflict-free LDSM phases; all multiples of 16B)
#define SAP   40               // A tile ldm (elems): 80B row stride
#define SBP   136              // B tile ldm (elems): 272B row stride
#define SPP   88               // proj B tile ldm (elems): 176B row stride

// ---------------- scratch (static device globals) ---------------------------
__device__ __nv_bfloat16 g_fnorm[MROW * CDIM];     // LN(feat)  bf16
__device__ __nv_bfloat16 g_qnorm[MROW * CDIM];     // LN(query) bf16
__device__ __nv_bfloat16 g_value[MROW * CDIM];     // value = fnorm@Wv+bv (bf16)
__device__ __nv_bfloat16 g_samp [MROW * CDIM];     // sampled attention (bf16)
__device__ float         g_s    [MROW * NPROJ];    // raw proj logits (no bias)
__device__ __nv_bfloat16 g_WvB  [CDIM * CDIM];
__device__ __nv_bfloat16 g_WoutB[CDIM * CDIM];
__device__ __nv_bfloat16 g_Wproj[CDIM * NPROJ];    // [Wo | Wa | 0pad]

// ---------------------------------------------------------------- cp.async
__device__ __forceinline__ void cp_async16(void* smem, const void* gmem) {
    unsigned int s = (unsigned int)__cvta_generic_to_shared(smem);
    asm volatile("cp.async.cg.shared.global [%0], [%1], 16;\n" :: "r"(s), "l"(gmem));
}
__device__ __forceinline__ void cp_commit() {
    asm volatile("cp.async.commit_group;\n");
}
template<int N> __device__ __forceinline__ void cp_wait() {
    asm volatile("cp.async.wait_group %0;\n" :: "n"(N));
}

__device__ __forceinline__ float warpReduceSum(float v) {
    #pragma unroll
    for (int o = 16; o > 0; o >>= 1) v += __shfl_xor_sync(0xffffffffu, v, o);
    return v;
}

// ---------------------------------------------------------- shared layouts
struct GemmSmem {
    __nv_bfloat16 sA[3][128 * SAP];
    __nv_bfloat16 sB[3][32 * SBP];
    float         sC[8][256];
};
struct ProjSmem {
    __nv_bfloat16 As[2][128 * SAP];
    __nv_bfloat16 Bs[2][32 * SPP];
    float         Cs[8][256];
};
union MidSmem { GemmSmem g; ProjSmem p; };

// ------------------------------------------------------------- layernorm
// one merged launch: blocks [0, MROW) -> feat, [MROW, 2*MROW) -> query
__global__ void ln_kernel(const float* __restrict__ feat,
                          const float* __restrict__ query,
                          const float* __restrict__ gf, const float* __restrict__ bf_,
                          const float* __restrict__ gq, const float* __restrict__ bq)
{
    const bool isq = blockIdx.x >= MROW;
    const int row  = isq ? (blockIdx.x - MROW) : blockIdx.x;
    const float* __restrict__ x = isq ? query : feat;
    const float* __restrict__ g = isq ? gq : gf;
    const float* __restrict__ b = isq ? bq : bf_;
    __nv_bfloat16* dst = isq ? g_qnorm : g_fnorm;

    const float* xr = x + (size_t)row * CDIM;
    const int t = threadIdx.x;

    float v0 = xr[t], v1 = xr[t + 128], v2 = xr[t + 256];
    float s  = v0 + v1 + v2;
    float sq = v0*v0 + v1*v1 + v2*v2;

    __shared__ float sh[8];
    s  = warpReduceSum(s);
    sq = warpReduceSum(sq);
    const int w = t >> 5;
    if ((t & 31) == 0) { sh[w] = s; sh[w + 4] = sq; }
    __syncthreads();
    if (t < 32) {
        float a = (t < 4) ? sh[t]     : 0.f;
        float c = (t < 4) ? sh[t + 4] : 0.f;
        a = warpReduceSum(a);
        c = warpReduceSum(c);
        if (t == 0) { sh[0] = a; sh[1] = c; }
    }
    __syncthreads();

    const float mu   = sh[0] * (1.f / CDIM);
    const float var  = sh[1] * (1.f / CDIM) - mu * mu;
    const float rstd = rsqrtf(var + 1e-6f);

    #pragma unroll
    for (int e = 0; e < 3; e++) {
        const int i = t + e * 128;
        const float v = (e == 0) ? v0 : (e == 1) ? v1 : v2;
        dst[(size_t)row * CDIM + i] = __float2bfloat16((v - mu) * rstd * g[i] + b[i]);
    }
}

// ------------------------------------------------------- weight conversion
__global__ void cvt_kernel(const float* __restrict__ Wv,
                           const float* __restrict__ Wout,
                           const float* __restrict__ Wo,
                           const float* __restrict__ Wa)
{
    const int i = blockIdx.x * blockDim.x + threadIdx.x;
    if (i < CDIM * CDIM) {
        g_WvB[i]   = __float2bfloat16(Wv[i]);
        g_WoutB[i] = __float2bfloat16(Wout[i]);
    }
    if (i < CDIM * NPROJ) {
        const int k = i / NPROJ, c = i % NPROJ;
        float v = 0.f;
        if (c < 48)      v = Wo[k * 48 + c];
        else if (c < 72) v = Wa[k * 24 + (c - 48)];
        g_Wproj[i] = __float2bfloat16(v);
    }
}

// --------------------------- gemm0 body: g_value = g_fnorm @ g_WvB + bv ------
// BM=128 BN=128 BK=32, 3-stage cp.async, padded smem. 8 warps = 4(M) x 2(N).
__device__ __forceinline__ void gemm0_body(GemmSmem& sm, int bx, int by,
                                           const float* __restrict__ bias)
{
    const __nv_bfloat16* __restrict__ A  = g_fnorm;
    const __nv_bfloat16* __restrict__ Bm = g_WvB;

    const int bm   = bx * 128;
    const int bn   = by * 128;
    const int tid  = threadIdx.x;
    const int wid  = tid >> 5;
    const int lane = tid & 31;
    const int wm   = wid & 3;
    const int wn   = wid >> 2;

    const int a_r0 = tid >> 2,            a_o0 = (tid & 3) << 3;
    const int a_r1 = (tid + 256) >> 2;
    const int b_r0 = tid >> 4,            b_o0 = (tid & 15) << 3;
    const int b_r1 = (tid + 256) >> 4;

    auto load_stage = [&](int st, int k0) {
        cp_async16(&sm.sA[st][a_r0 * SAP + a_o0], A  + (size_t)(bm + a_r0) * CDIM + k0 + a_o0);
        cp_async16(&sm.sA[st][a_r1 * SAP + a_o0], A  + (size_t)(bm + a_r1) * CDIM + k0 + a_o0);
        cp_async16(&sm.sB[st][b_r0 * SBP + b_o0], Bm + (size_t)(k0 + b_r0) * CDIM + bn + b_o0);
        cp_async16(&sm.sB[st][b_r1 * SBP + b_o0], Bm + (size_t)(k0 + b_r1) * CDIM + bn + b_o0);
        cp_commit();
    };

    wmma::fragment<wmma::accumulator, 16, 16, 16, float> acc[2][4];
    #pragma unroll
    for (int i = 0; i < 2; i++)
        #pragma unroll
        for (int j = 0; j < 4; j++)
            wmma::fill_fragment(acc[i][j], 0.0f);

    load_stage(0, 0);
    load_stage(1, 32);

    const int KIT = CDIM / 32;   // 12
    for (int k = 0; k < KIT; k++) {
        cp_wait<1>();
        __syncthreads();
        const int st = k % 3;

        if (k + 2 < KIT) load_stage((k + 2) % 3, (k + 2) * 32);
        else             cp_commit();

        #pragma unroll
        for (int kk = 0; kk < 2; kk++) {
            wmma::fragment<wmma::matrix_a, 16, 16, 16, __nv_bfloat16, wmma::row_major> af[2];
            wmma::fragment<wmma::matrix_b, 16, 16, 16, __nv_bfloat16, wmma::row_major> bf;
            wmma::load_matrix_sync(af[0], &sm.sA[st][(wm * 32     ) * SAP + kk * 16], SAP);
            wmma::load_matrix_sync(af[1], &sm.sA[st][(wm * 32 + 16) * SAP + kk * 16], SAP);
            #pragma unroll
            for (int j = 0; j < 4; j++) {
                wmma::load_matrix_sync(bf, &sm.sB[st][(kk * 16) * SBP + wn * 64 + j * 16], SBP);
                wmma::mma_sync(acc[0][j], af[0], bf, acc[0][j]);
                wmma::mma_sync(acc[1][j], af[1], bf, acc[1][j]);
            }
        }
    }

    cp_wait<0>();
    __syncthreads();

    #pragma unroll
    for (int im = 0; im < 2; im++) {
        #pragma unroll
        for (int j = 0; j < 4; j++) {
            wmma::store_matrix_sync(sm.sC[wid], acc[im][j], 16, wmma::mem_row_major);
            __syncwarp();
            const int r  = lane >> 1;
            const int c0 = (lane & 1) << 3;
            const int gm = bm + wm * 32 + im * 16 + r;
            const int gn = bn + wn * 64 + j * 16 + c0;
            union { __nv_bfloat16 h[8]; uint4 u; } t;
            #pragma unroll
            for (int cc = 0; cc < 8; cc++)
                t.h[cc] = __float2bfloat16(sm.sC[wid][r * 16 + c0 + cc] + bias[gn + cc]);
            *(uint4*)&g_value[(size_t)gm * CDIM + gn] = t.u;
            __syncwarp();
        }
    }
}

// --------------------------- proj body: g_s = g_qnorm @ g_Wproj --------------
// BM=128 BN=80 BK=32, 2-stage cp.async, padded smem. 8 warps, each 16x80.
__device__ __forceinline__ void proj_body(ProjSmem& sm, int bx)
{
    const int bm   = bx * 128;
    const int tid  = threadIdx.x;
    const int wid  = tid >> 5;
    const int lane = tid & 31;

    const int a_r0 = tid >> 2,         a_o = (tid & 3) << 3;
    const int a_r1 = (tid + 256) >> 2;

    auto load_stage = [&](int st, int k0) {
        cp_async16(&sm.As[st][a_r0 * SAP + a_o], g_qnorm + (size_t)(bm + a_r0) * CDIM + k0 + a_o);
        cp_async16(&sm.As[st][a_r1 * SAP + a_o], g_qnorm + (size_t)(bm + a_r1) * CDIM + k0 + a_o);
        {
            const int c = tid;
            if (c < 320) {
                const int r = c / 10, o = (c % 10) << 3;
                cp_async16(&sm.Bs[st][r * SPP + o], g_Wproj + (size_t)(k0 + r) * NPROJ + o);
            }
            const int c2 = tid + 256;
            if (c2 < 320) {
                const int r = c2 / 10, o = (c2 % 10) << 3;
                cp_async16(&sm.Bs[st][r * SPP + o], g_Wproj + (size_t)(k0 + r) * NPROJ + o);
            }
        }
        cp_commit();
    };

    wmma::fragment<wmma::accumulator, 16, 16, 16, float> acc[5];
    #pragma unroll
    for (int j = 0; j < 5; j++) wmma::fill_fragment(acc[j], 0.0f);

    load_stage(0, 0);
    const int KIT = CDIM / 32;   // 12
    for (int k = 0; k < KIT; k++) {
        cp_wait<0>();
        __syncthreads();
        const int st = k & 1;
        if (k + 1 < KIT) load_stage((k + 1) & 1, (k + 1) * 32);

        #pragma unroll
        for (int kk = 0; kk < 2; kk++) {
            wmma::fragment<wmma::matrix_a, 16, 16, 16, __nv_bfloat16, wmma::row_major> af;
            wmma::fragment<wmma::matrix_b, 16, 16, 16, __nv_bfloat16, wmma::row_major> bf;
            wmma::load_matrix_sync(af, &sm.As[st][(wid * 16) * SAP + kk * 16], SAP);
            #pragma unroll
            for (int j = 0; j < 5; j++) {
                wmma::load_matrix_sync(bf, &sm.Bs[st][(kk * 16) * SPP + j * 16], SPP);
                wmma::mma_sync(acc[j], af, bf, acc[j]);
            }
        }
    }

    cp_wait<0>();
    __syncthreads();

    #pragma unroll
    for (int j = 0; j < 5; j++) {
        wmma::store_matrix_sync(sm.Cs[wid], acc[j], 16, wmma::mem_row_major);
        __syncwarp();
        const int r  = lane >> 1;
        const int c0 = (lane & 1) << 3;
        const int gm = bm + wid * 16 + r;
        const int gn = j * 16 + c0;
        #pragma unroll
        for (int cc = 0; cc < 8; cc++)
            g_s[(size_t)gm * NPROJ + gn + cc] = sm.Cs[wid][r * 16 + c0 + cc];
        __syncwarp();
    }
}

// ------------------------- merged mid kernel: gemm0 tiles + proj tiles -------
// grid (128, 4): y in [0,3) -> gemm0 tile (bm=x*128, bn=y*128); y==3 -> proj tile.
__global__ __launch_bounds__(256)
void mid_kernel(const float* __restrict__ bv)
{
    __shared__ MidSmem sm;
    if (blockIdx.y < 3) gemm0_body(sm.g, blockIdx.x, blockIdx.y, bv);
    else                proj_body(sm.p, blockIdx.x);
}

// --------------------------- final GEMM: out = query + gamma*(samp@Wout+bout)
__global__ __launch_bounds__(256)
void gemm1_kernel(const float* __restrict__ bias,
                  const float* __restrict__ query,
                  const float* __restrict__ gamma,
                  float* __restrict__ out)
{
    const __nv_bfloat16* __restrict__ A  = g_samp;
    const __nv_bfloat16* __restrict__ Bm = g_WoutB;

    __shared__ GemmSmem sm;

    const int bm   = blockIdx.x * 128;
    const int bn   = blockIdx.y * 128;
    const int tid  = threadIdx.x;
    const int wid  = tid >> 5;
    const int lane = tid & 31;
    const int wm   = wid & 3;
    const int wn   = wid >> 2;

    const int a_r0 = tid >> 2,            a_o0 = (tid & 3) << 3;
    const int a_r1 = (tid + 256) >> 2;
    const int b_r0 = tid >> 4,            b_o0 = (tid & 15) << 3;
    const int b_r1 = (tid + 256) >> 4;

    auto load_stage = [&](int st, int k0) {
        cp_async16(&sm.sA[st][a_r0 * SAP + a_o0], A  + (size_t)(bm + a_r0) * CDIM + k0 + a_o0);
        cp_async16(&sm.sA[st][a_r1 * SAP + a_o0], A  + (size_t)(bm + a_r1) * CDIM + k0 + a_o0);
        cp_async16(&sm.sB[st][b_r0 * SBP + b_o0], Bm + (size_t)(k0 + b_r0) * CDIM + bn + b_o0);
        cp_async16(&sm.sB[st][b_r1 * SBP + b_o0], Bm + (size_t)(k0 + b_r1) * CDIM + bn + b_o0);
        cp_commit();
    };

    wmma::fragment<wmma::accumulator, 16, 16, 16, float> acc[2][4];
    #pragma unroll
    for (int i = 0; i < 2; i++)
        #pragma unroll
        for (int j = 0; j < 4; j++)
            wmma::fill_fragment(acc[i][j], 0.0f);

    load_stage(0, 0);
    load_stage(1, 32);

    const int KIT = CDIM / 32;   // 12
    for (int k = 0; k < KIT; k++) {
        cp_wait<1>();
        __syncthreads();
        const int st = k % 3;

        if (k + 2 < KIT) load_stage((k + 2) % 3, (k + 2) * 32);
        else             cp_commit();

        #pragma unroll
        for (int kk = 0; kk < 2; kk++) {
            wmma::fragment<wmma::matrix_a, 16, 16, 16, __nv_bfloat16, wmma::row_major> af[2];
            wmma::fragment<wmma::matrix_b, 16, 16, 16, __nv_bfloat16, wmma::row_major> bf;
            wmma::load_matrix_sync(af[0], &sm.sA[st][(wm * 32     ) * SAP + kk * 16], SAP);
            wmma::load_matrix_sync(af[1], &sm.sA[st][(wm * 32 + 16) * SAP + kk * 16], SAP);
            #pragma unroll
            for (int j = 0; j < 4; j++) {
                wmma::load_matrix_sync(bf, &sm.sB[st][(kk * 16) * SBP + wn * 64 + j * 16], SBP);
                wmma::mma_sync(acc[0][j], af[0], bf, acc[0][j]);
                wmma::mma_sync(acc[1][j], af[1], bf, acc[1][j]);
            }
        }
    }

    cp_wait<0>();
    __syncthreads();

    #pragma unroll
    for (int im = 0; im < 2; im++) {
        #pragma unroll
        for (int j = 0; j < 4; j++) {
            wmma::store_matrix_sync(sm.sC[wid], acc[im][j], 16, wmma::mem_row_major);
            __syncwarp();
            const int r  = lane >> 1;
            const int c0 = (lane & 1) << 3;
            const int gm = bm + wm * 32 + im * 16 + r;
            const int gn = bn + wn * 64 + j * 16 + c0;
            const size_t base = (size_t)gm * CDIM + gn;
            float4 q0 = *(const float4*)&query[base];
            float4 q1 = *(const float4*)&query[base + 4];
            float4 o0, o1;
            o0.x = q0.x + gamma[gn+0] * (sm.sC[wid][r*16+c0+0] + bias[gn+0]);
            o0.y = q0.y + gamma[gn+1] * (sm.sC[wid][r*16+c0+1] + bias[gn+1]);
            o0.z = q0.z + gamma[gn+2] * (sm.sC[wid][r*16+c0+2] + bias[gn+2]);
            o0.w = q0.w + gamma[gn+3] * (sm.sC[wid][r*16+c0+3] + bias[gn+3]);
            o1.x = q1.x + gamma[gn+4] * (sm.sC[wid][r*16+c0+4] + bias[gn+4]);
            o1.y = q1.y + gamma[gn+5] * (sm.sC[wid][r*16+c0+5] + bias[gn+5]);
            o1.z = q1.z + gamma[gn+6] * (sm.sC[wid][r*16+c0+6] + bias[gn+6]);
            o1.w = q1.w + gamma[gn+7] * (sm.sC[wid][r*16+c0+7] + bias[gn+7]);
            *(float4*)&out[base]     = o0;
            *(float4*)&out[base + 4] = o1;
            __syncwarp();
        }
    }
}

// ------------------------------ sampling (softmax + locations fused) --------
// blockDim (16,16): lane = uint2 (4 channels), y-slot = (row,head) unit.
// Fewer, wider gathers: halves instruction streams vs the 2-channel version.
__global__ __launch_bounds__(256)
void sample_kernel(const float* __restrict__ bo,
                   const float* __restrict__ ba,
                   const float* __restrict__ refp)
{
    const int lane = threadIdx.x;                    // 0..15, 4 channels each
    const int u = blockIdx.x * 16 + threadIdx.y;     // 0 .. MROW*NH-1
    const int h   = u % NH;
    const int row = u / NH;
    const int b   = row >> 12;

    const float rx = refp[(size_t)row * 2 + 0] * 64.f - 0.5f;
    const float ry = refp[(size_t)row * 2 + 1] * 64.f - 0.5f;
    const float* srow = g_s + (size_t)row * NPROJ;

    // softmax over the head's 4 attention logits
    float aw[NP]; float m = -1e30f;
    #pragma unroll
    for (int p = 0; p < NP; p++) {
        aw[p] = srow[48 + h * NP + p] + ba[h * NP + p];
        m = fmaxf(m, aw[p]);
    }
    float ssum = 0.f;
    #pragma unroll
    for (int p = 0; p < NP; p++) { aw[p] = __expf(aw[p] - m); ssum += aw[p]; }
    const float inv = 1.f / ssum;

    // uint2 view: each lane handles channels {4*lane .. 4*lane+3} of this head
    const uint2* __restrict__ vb =
        (const uint2*)(g_value + (size_t)b * LV * CDIM + h * DH) + lane;
    float acc0 = 0.f, acc1 = 0.f, acc2 = 0.f, acc3 = 0.f;

    #pragma unroll
    for (int p = 0; p < NP; p++) {
        // loc*64 - 0.5 == ref*64 + offset - 0.5 (W == H == 64 cancels the /64)
        const float x = rx + srow[h * 8 + p * 2 + 0] + bo[h * 8 + p * 2 + 0];
        const float y = ry + srow[h * 8 + p * 2 + 1] + bo[h * 8 + p * 2 + 1];
        const float w = aw[p] * inv;
        const float x0f = floorf(x), y0f = floorf(y);
        const int   x0 = (int)x0f,  y0 = (int)y0f;
        const float wx = x - x0f,   wy = y - y0f;

        const bool xin0 = (x0 >= 0) & (x0 < WL), xin1 = (x0+1 >= 0) & (x0+1 < WL);
        const bool yin0 = (y0 >= 0) & (y0 < HL), yin1 = (y0+1 >= 0) & (y0+1 < HL);

        #pragma unroll
        for (int c = 0; c < 4; c++) {
            const int  xi = x0 + (c & 1),  yi = y0 + (c >> 1);
            const bool ok = (c & 1 ? xin1 : xin0) & (c >> 1 ? yin1 : yin0);
            if (ok) {
                const float cw = ((c & 1) ? wx : 1.f - wx) * ((c >> 1) ? wy : 1.f - wy) * w;
                const unsigned int off = (unsigned int)(yi * WL + xi) * (CDIM / 4);
                const uint2 pk = vb[off];
                const __nv_bfloat162 vlo = *(const __nv_bfloat162*)&pk.x;
                const __nv_bfloat162 vhi = *(const __nv_bfloat162*)&pk.y;
                acc0 += cw * __bfloat162float(vlo.x);
                acc1 += cw * __bfloat162float(vlo.y);
                acc2 += cw * __bfloat162float(vhi.x);
                acc3 += cw * __bfloat162float(vhi.y);
            }
        }
    }
    union { __nv_bfloat16 h4[4]; uint2 u2; } o;
    o.h4[0] = __float2bfloat16(acc0);
    o.h4[1] = __float2bfloat16(acc1);
    o.h4[2] = __float2bfloat16(acc2);
    o.h4[3] = __float2bfloat16(acc3);
    *(uint2*)&g_samp[(size_t)row * CDIM + h * DH + lane * 4] = o.u2;
}

// ------------------------------------------------------------------- launch
extern "C" void kernel_launch(void* const* d_in, const int* in_sizes, int n_in,
                              void* d_out, int out_size)
{
    const float* query  = (const float*)d_in[0];
    const float* refp   = (const float*)d_in[1];
    const float* feat   = (const float*)d_in[2];
    const float* ln_q_g = (const float*)d_in[5];
    const float* ln_q_b = (const float*)d_in[6];
    const float* ln_f_g = (const float*)d_in[7];
    const float* ln_f_b = (const float*)d_in[8];
    const float* gamma  = (const float*)d_in[9];
    const float* Wv     = (const float*)d_in[10];
    const float* bv     = (const float*)d_in[11];
    const float* Wo     = (const float*)d_in[12];
    const float* bo     = (const float*)d_in[13];
    const float* Wa     = (const float*)d_in[14];
    const float* ba     = (const float*)d_in[15];
    const float* Wout   = (const float*)d_in[16];
    const float* bout   = (const float*)d_in[17];
    float* out = (float*)d_out;

    ln_kernel<<<2 * MROW, 128>>>(feat, query, ln_f_g, ln_f_b, ln_q_g, ln_q_b);
    cvt_kernel<<<(CDIM * CDIM + 255) / 256, 256>>>(Wv, Wout, Wo, Wa);

    mid_kernel<<<dim3(MROW / 128, 4), 256>>>(bv);                 // gemm0 + proj
    sample_kernel<<<(MROW * NH) / 16, dim3(16, 16)>>>(bo, ba, refp);
    gemm1_kernel<<<dim3(MROW / 128, CDIM / 128), 256>>>(bout, query, gamma, out);
}